// round 13
// baseline (speedup 1.0000x reference)
#include <cuda_runtime.h>
#include <cuda_bf16.h>
#include <math.h>

#define BB 4
#define SS 1024
#define DD 1024
#define HH 16
#define HD 64
#define MROWS (BB*SS)

// ---------------- scratch (device globals; no allocation) ----------------
__device__ float g_local[MROWS*DD];
__device__ float g_gout[MROWS*DD];
__device__ float g_base[BB];
__device__ float g_pp[BB*16*DD];

// bf16 hi/lo planes
__device__ __nv_bfloat16 gb_globe_h[MROWS*DD], gb_globe_l[MROWS*DD];
__device__ __nv_bfloat16 gb_q_h[MROWS*DD],    gb_q_l[MROWS*DD];
__device__ __nv_bfloat16 gb_k_h[MROWS*DD],    gb_k_l[MROWS*DD];
__device__ __nv_bfloat16 gb_v_h[MROWS*DD],    gb_v_l[MROWS*DD];   // transposed [b][h][d][s]
__device__ __nv_bfloat16 gb_attn_h[MROWS*DD], gb_attn_l[MROWS*DD];
__device__ __nv_bfloat16 gb_gout_h[MROWS*DD], gb_gout_l[MROWS*DD];
__device__ __nv_bfloat16 gb_lout_h[MROWS*DD], gb_lout_l[MROWS*DD];
__device__ __nv_bfloat16 gb_wq_h[DD*DD], gb_wq_l[DD*DD];
__device__ __nv_bfloat16 gb_wk_h[DD*DD], gb_wk_l[DD*DD];
__device__ __nv_bfloat16 gb_wv_h[DD*DD], gb_wv_l[DD*DD];
__device__ __nv_bfloat16 gb_wo_h[DD*DD], gb_wo_l[DD*DD];
__device__ __nv_bfloat16 gb_wp_h[DD*2*DD], gb_wp_l[DD*2*DD];

struct SpanParams {
    int win, span_len, local_max;
    float span_mean, temp;
};
__device__ SpanParams g_params;

// ---------------- helpers ----------------
__device__ __forceinline__ void split_pack(float x0, float x1, unsigned &hi, unsigned &lo)
{
    __nv_bfloat16 h0 = __float2bfloat16(x0);
    __nv_bfloat16 h1 = __float2bfloat16(x1);
    float f0 = __bfloat162float(h0), f1 = __bfloat162float(h1);
    __nv_bfloat16 l0 = __float2bfloat16(x0 - f0);
    __nv_bfloat16 l1 = __float2bfloat16(x1 - f1);
    hi = ((unsigned)__bfloat16_as_ushort(h1) << 16) | (unsigned)__bfloat16_as_ushort(h0);
    lo = ((unsigned)__bfloat16_as_ushort(l1) << 16) | (unsigned)__bfloat16_as_ushort(l0);
}

__device__ __forceinline__ void split_store(float v, __nv_bfloat16* hi, __nv_bfloat16* lo, size_t idx)
{
    __nv_bfloat16 h = __float2bfloat16(v);
    hi[idx] = h;
    lo[idx] = __float2bfloat16(v - __bfloat162float(h));
}

__device__ __forceinline__ void mma_bf16(float c[4],
                                         unsigned a0, unsigned a1, unsigned a2, unsigned a3,
                                         unsigned b0, unsigned b1)
{
    asm volatile("mma.sync.aligned.m16n8k16.row.col.f32.bf16.bf16.f32 "
                 "{%0,%1,%2,%3}, {%4,%5,%6,%7}, {%8,%9}, {%0,%1,%2,%3};"
                 : "+f"(c[0]), "+f"(c[1]), "+f"(c[2]), "+f"(c[3])
                 : "r"(a0), "r"(a1), "r"(a2), "r"(a3), "r"(b0), "r"(b1));
}

__device__ __forceinline__ void ldsm4(unsigned &r0, unsigned &r1, unsigned &r2, unsigned &r3, unsigned addr)
{
    asm volatile("ldmatrix.sync.aligned.m8n8.x4.shared.b16 {%0,%1,%2,%3}, [%4];"
                 : "=r"(r0), "=r"(r1), "=r"(r2), "=r"(r3) : "r"(addr));
}

__device__ __forceinline__ void cpa16(unsigned saddr, const void* g)
{
    asm volatile("cp.async.ca.shared.global [%0], [%1], 16;" :: "r"(saddr), "l"(g));
}

// ---------------- merged weight split (all 5 weights, 1 launch) ----------
#define W1M4 (DD*DD/4)
#define W2M4 (DD*2*DD/4)
__global__ void conv_split_all(const float4* __restrict__ wq, const float4* __restrict__ wk,
                               const float4* __restrict__ wv, const float4* __restrict__ wo,
                               const float4* __restrict__ wp)
{
    int i = blockIdx.x * blockDim.x + threadIdx.x;
    const float4* src;
    __nv_bfloat16 *hi, *lo;
    int off;
    if (i < W1M4)            { src = wq; hi = gb_wq_h; lo = gb_wq_l; off = i; }
    else if (i < 2*W1M4)     { src = wk; hi = gb_wk_h; lo = gb_wk_l; off = i - W1M4; }
    else if (i < 3*W1M4)     { src = wv; hi = gb_wv_h; lo = gb_wv_l; off = i - 2*W1M4; }
    else if (i < 4*W1M4)     { src = wo; hi = gb_wo_h; lo = gb_wo_l; off = i - 3*W1M4; }
    else if (i < 4*W1M4+W2M4){ src = wp; hi = gb_wp_h; lo = gb_wp_l; off = i - 4*W1M4; }
    else return;
    float4 v = src[off];
    unsigned h0, l0, h1, l1;
    split_pack(v.x, v.y, h0, l0);
    split_pack(v.z, v.w, h1, l1);
    *(uint2*)(hi + (size_t)off*4) = make_uint2(h0, h1);
    *(uint2*)(lo + (size_t)off*4) = make_uint2(l0, l1);
}

// ---------------- LayerNorm: fp32 local + bf16 hi/lo globe ----------------
__global__ void ln_kernel(const float* __restrict__ x,
                          const float* __restrict__ ga, const float* __restrict__ ba,
                          const float* __restrict__ gb, const float* __restrict__ bb)
{
    __shared__ float red[256];
    int row = blockIdx.x;
    int t = threadIdx.x;
    const float* xr = x + (size_t)row * DD;
    float v[4];
    float s = 0.f;
#pragma unroll
    for (int k = 0; k < 4; k++) { v[k] = xr[t + 256*k]; s += v[k]; }
    red[t] = s; __syncthreads();
    for (int o = 128; o > 0; o >>= 1) { if (t < o) red[t] += red[t+o]; __syncthreads(); }
    float mean = red[0] * (1.0f/DD);
    __syncthreads();
    float s2 = 0.f;
#pragma unroll
    for (int k = 0; k < 4; k++) { float d0 = v[k]-mean; s2 += d0*d0; }
    red[t] = s2; __syncthreads();
    for (int o = 128; o > 0; o >>= 1) { if (t < o) red[t] += red[t+o]; __syncthreads(); }
    float rs = rsqrtf(red[0]*(1.0f/DD) + 1e-5f);
#pragma unroll
    for (int k = 0; k < 4; k++) {
        int c = t + 256*k;
        float nh = (v[k]-mean)*rs;
        size_t idx = (size_t)row*DD + c;
        g_local[idx] = nh*ga[c] + ba[c];
        split_store(nh*gb[c] + bb[c], gb_globe_h, gb_globe_l, idx);
    }
}

// ---------------- bf16x3 GEMM: swizzled smem, 3-stage cp.async (.ca) ------
// C[M,N] = (A | A2)[M, K] @ (Wh+Wl)[N, koff:koff+K]^T, drop lo*lo.
// A switches from (Ah,Al) to (A2h,A2l) at chunk k1ch (dual-A fusion).
// 128x128 CTA, K-chunk 32, 8 warps 2(m)x4(n).
// smem: rows of 64B, 16B slot swizzle p = L ^ ((row>>1)&3). 4 planes x 8KB.
#define GST_PLANE 8192
#define GST_STAGE 32768
#define GEMM_SMEM_BYTES (3*GST_STAGE)

__global__ void __launch_bounds__(256, 2) gemm_bf16lm(
    const __nv_bfloat16* __restrict__ Ah, const __nv_bfloat16* __restrict__ Al,
    const __nv_bfloat16* __restrict__ A2h, const __nv_bfloat16* __restrict__ A2l,
    const __nv_bfloat16* __restrict__ Wh, const __nv_bfloat16* __restrict__ Wl,
    const float* __restrict__ bias, float* __restrict__ C,
    __nv_bfloat16* __restrict__ Chi, __nv_bfloat16* __restrict__ Clo,
    int N, int lda, int K, int ldw, int koff, int k1ch, int transv)
{
    extern __shared__ char sm8[];
    unsigned sbase = (unsigned)__cvta_generic_to_shared(sm8);

    int t = threadIdx.x;
    int wid = t >> 5, lane = t & 31;
    int warp_m = wid >> 2, warp_n = wid & 3;
    int bm = blockIdx.y * 128, bn = blockIdx.x * 128;
    int qq = lane >> 2, rr = lane & 3;

    // cp.async layout: thread -> (row = t>>1, 32B span = (t&1))
    int crow = t >> 1;
    int csp = t & 1;
    const __nv_bfloat16* gAh = Ah + (size_t)(bm + crow) * lda + csp*16;
    const __nv_bfloat16* gAl = Al + (size_t)(bm + crow) * lda + csp*16;
    const __nv_bfloat16* gA2h = A2h ? A2h + (size_t)(bm + crow) * lda + csp*16 : gAh;
    const __nv_bfloat16* gA2l = A2l ? A2l + (size_t)(bm + crow) * lda + csp*16 : gAl;
    const __nv_bfloat16* gWh = Wh + (size_t)(bn + crow) * ldw + koff + csp*16;
    const __nv_bfloat16* gWl = Wl + (size_t)(bn + crow) * ldw + koff + csp*16;
    unsigned swzr = ((unsigned)crow >> 1) & 3u;
    unsigned p0 = ((unsigned)(2*csp)) ^ swzr;
    unsigned dOff0 = (unsigned)crow*64u + (p0 << 4);
    unsigned dOff1 = (unsigned)crow*64u + ((p0 ^ 1u) << 4);

    // ldmatrix lane addressing (ks=0 base offsets; ks=1 via XOR 32)
    int mq = lane >> 3, j = lane & 7;
    unsigned swz = (((unsigned)j) >> 1) & 3u;
    unsigned aOffH = (unsigned)(warp_m*64 + (mq&1)*8 + j) * 64u
                   + ((((unsigned)(mq>>1)) ^ swz) << 4);
    unsigned bOffH = (unsigned)(warp_n*32 + (mq>>1)*8 + j) * 64u
                   + ((((unsigned)(mq&1)) ^ swz) << 4);

    float acc[4][4][4];
#pragma unroll
    for (int im = 0; im < 4; im++)
#pragma unroll
        for (int in = 0; in < 4; in++)
#pragma unroll
            for (int r = 0; r < 4; r++) acc[im][in][r] = 0.f;

#define ISSUE(buf, kc) do { \
    unsigned sb_ = sbase + (buf)*GST_STAGE; \
    const __nv_bfloat16* sh_ = ((kc) < k1ch) ? gAh + (size_t)(kc)*32 : gA2h + (size_t)((kc) - k1ch)*32; \
    const __nv_bfloat16* sl_ = ((kc) < k1ch) ? gAl + (size_t)(kc)*32 : gA2l + (size_t)((kc) - k1ch)*32; \
    cpa16(sb_ + dOff0,               sh_); \
    cpa16(sb_ + dOff1,               sh_ + 8); \
    cpa16(sb_ + GST_PLANE + dOff0,   sl_); \
    cpa16(sb_ + GST_PLANE + dOff1,   sl_ + 8); \
    cpa16(sb_ + 2*GST_PLANE + dOff0, gWh + (size_t)(kc)*32); \
    cpa16(sb_ + 2*GST_PLANE + dOff1, gWh + (size_t)(kc)*32 + 8); \
    cpa16(sb_ + 3*GST_PLANE + dOff0, gWl + (size_t)(kc)*32); \
    cpa16(sb_ + 3*GST_PLANE + dOff1, gWl + (size_t)(kc)*32 + 8); \
    asm volatile("cp.async.commit_group;"); \
} while (0)

    int nch = K / 32;
    ISSUE(0, 0);
    if (nch > 1) ISSUE(1, 1);

    int cur = 0;
    for (int c = 0; c < nch; c++) {
        if (c + 1 < nch) asm volatile("cp.async.wait_group 1;");
        else             asm volatile("cp.async.wait_group 0;");
        __syncthreads();
        // prefetch chunk c+2 into the stage drained at iteration c-1
        if (c + 2 < nch) {
            int nxt = cur + 2; if (nxt >= 3) nxt -= 3;
            ISSUE(nxt, c + 2);
        }
        unsigned sb = sbase + cur*GST_STAGE;
#pragma unroll
        for (int ks = 0; ks < 2; ks++) {
            unsigned kx = ks ? 32u : 0u;
            unsigned bh0[4], bh1[4], bl0[4], bl1[4];
            {
                unsigned r0,r1,r2,r3;
                unsigned ba = sb + 2*GST_PLANE + (bOffH ^ kx);
                ldsm4(r0,r1,r2,r3, ba);
                bh0[0]=r0; bh1[0]=r1; bh0[1]=r2; bh1[1]=r3;
                ldsm4(r0,r1,r2,r3, ba + 1024);
                bh0[2]=r0; bh1[2]=r1; bh0[3]=r2; bh1[3]=r3;
                unsigned bb = sb + 3*GST_PLANE + (bOffH ^ kx);
                ldsm4(r0,r1,r2,r3, bb);
                bl0[0]=r0; bl1[0]=r1; bl0[1]=r2; bl1[1]=r3;
                ldsm4(r0,r1,r2,r3, bb + 1024);
                bl0[2]=r0; bl1[2]=r1; bl0[3]=r2; bl1[3]=r3;
            }
#pragma unroll
            for (int im = 0; im < 4; im++) {
                unsigned ah0,ah1,ah2,ah3, al0,al1,al2,al3;
                unsigned aa = sb + (aOffH ^ kx) + im*1024;
                ldsm4(ah0,ah1,ah2,ah3, aa);
                ldsm4(al0,al1,al2,al3, aa + GST_PLANE);
#pragma unroll
                for (int in = 0; in < 4; in++) {
                    mma_bf16(acc[im][in], ah0,ah1,ah2,ah3, bh0[in], bh1[in]);
                    mma_bf16(acc[im][in], ah0,ah1,ah2,ah3, bl0[in], bl1[in]);
                    mma_bf16(acc[im][in], al0,al1,al2,al3, bh0[in], bh1[in]);
                }
            }
        }
        cur++; if (cur >= 3) cur -= 3;
    }
#undef ISSUE

    // epilogue
#pragma unroll
    for (int im = 0; im < 4; im++) {
        int r0 = bm + warp_m*64 + im*16 + qq;
#pragma unroll
        for (int in = 0; in < 4; in++) {
            int c0 = bn + warp_n*32 + in*8 + 2*rr;
            float b0v = bias ? bias[c0]   : 0.f;
            float b1v = bias ? bias[c0+1] : 0.f;
#pragma unroll
            for (int half = 0; half < 2; half++) {
                int m = r0 + half*8;
                float v0 = acc[im][in][2*half + 0] + b0v;
                float v1 = acc[im][in][2*half + 1] + b1v;
                if (transv) {
                    size_t i0 = ((size_t)((m>>10)*HH + (c0>>6))*HD + (c0&63))*SS + (m&1023);
                    size_t i1 = ((size_t)((m>>10)*HH + ((c0+1)>>6))*HD + ((c0+1)&63))*SS + (m&1023);
                    split_store(v0, Chi, Clo, i0);
                    split_store(v1, Chi, Clo, i1);
                } else {
                    size_t idx = (size_t)m * N + c0;
                    if (C) { C[idx] = v0; C[idx+1] = v1; }
                    if (Chi) {
                        split_store(v0, Chi, Clo, idx);
                        split_store(v1, Chi, Clo, idx+1);
                    }
                }
            }
        }
    }
}

// ---------------- Global causal attention (bf16x3 MMA, pre-split QKV) -----
#define AW 36
#define A_QH 0
#define A_QL 2304
#define A_KH 4608
#define A_KL 6912
#define A_PH 9216
#define A_PL 11520
#define A_ST 13824               // float [64][66]
#define A_MS (13824 + 4224)
#define ATT_SMEM_WORDS (13824 + 4224 + 192)
#define ATT_SMEM_BYTES (ATT_SMEM_WORDS*4)

__global__ void __launch_bounds__(256) attn_global_mma()
{
    extern __shared__ unsigned usm[];
    float* STm = (float*)(usm + A_ST);
    float* m_s = (float*)(usm + A_MS);
    float* l_s = m_s + 64;
    float* al_s = l_s + 64;

    int qt = 15 - (int)blockIdx.x;
    int bh = blockIdx.y;
    int b = bh >> 4, h = bh & 15;
    int t = threadIdx.x;
    int lane = t & 31, wid = t >> 5;
    int tx = t & 15, ty = t >> 4;
    int warp_m = wid & 3, warp_n = wid >> 2;
    int qq = lane >> 2, rr = lane & 3;
    int q0 = qt * 64;
    size_t baseQ = (size_t)b * SS * DD + h * HD;
    size_t baseVT = ((size_t)(b*HH + h)) * HD * SS;

#pragma unroll
    for (int i = 0; i < 4; i++) {
        int r = ty + 16*i;
        size_t gi = baseQ + (size_t)(q0 + r) * DD + 4*tx;
        uint2 vh = *(const uint2*)(gb_q_h + gi);
        uint2 vl = *(const uint2*)(gb_q_l + gi);
        usm[A_QH + r*AW + 2*tx] = vh.x;  usm[A_QH + r*AW + 2*tx + 1] = vh.y;
        usm[A_QL + r*AW + 2*tx] = vl.x;  usm[A_QL + r*AW + 2*tx + 1] = vl.y;
    }
    if (t < 64) { m_s[t] = -3.0e38f; l_s[t] = 0.f; }

    float oacc[4][4];
#pragma unroll
    for (int nn = 0; nn < 4; nn++)
#pragma unroll
        for (int r = 0; r < 4; r++) oacc[nn][r] = 0.f;

    __syncthreads();

    for (int kt = 0; kt <= qt; kt++) {
        int k0 = kt * 64;
#pragma unroll
        for (int i = 0; i < 4; i++) {
            int r = ty + 16*i;
            size_t gi = baseQ + (size_t)(k0 + r) * DD + 4*tx;
            uint2 vh = *(const uint2*)(gb_k_h + gi);
            uint2 vl = *(const uint2*)(gb_k_l + gi);
            usm[A_KH + r*AW + 2*tx] = vh.x;  usm[A_KH + r*AW + 2*tx + 1] = vh.y;
            usm[A_KL + r*AW + 2*tx] = vl.x;  usm[A_KL + r*AW + 2*tx + 1] = vl.y;
        }
        __syncthreads();

        // S^T = K @ Q^T
        {
            float c4[4][4];
#pragma unroll
            for (int nn = 0; nn < 4; nn++)
#pragma unroll
                for (int r = 0; r < 4; r++) c4[nn][r] = 0.f;
#pragma unroll
            for (int ks = 0; ks < 4; ks++) {
                int kw = ks*8;
                int ar = warp_m*16 + qq;
                unsigned ah0 = usm[A_KH +  ar   *AW + kw+rr];
                unsigned ah1 = usm[A_KH + (ar+8)*AW + kw+rr];
                unsigned ah2 = usm[A_KH +  ar   *AW + kw+4+rr];
                unsigned ah3 = usm[A_KH + (ar+8)*AW + kw+4+rr];
                unsigned al0 = usm[A_KL +  ar   *AW + kw+rr];
                unsigned al1 = usm[A_KL + (ar+8)*AW + kw+rr];
                unsigned al2 = usm[A_KL +  ar   *AW + kw+4+rr];
                unsigned al3 = usm[A_KL + (ar+8)*AW + kw+4+rr];
#pragma unroll
                for (int nn = 0; nn < 4; nn++) {
                    int br = warp_n*32 + nn*8 + qq;
                    unsigned bh0 = usm[A_QH + br*AW + kw+rr];
                    unsigned bh1 = usm[A_QH + br*AW + kw+4+rr];
                    unsigned bl0 = usm[A_QL + br*AW + kw+rr];
                    unsigned bl1 = usm[A_QL + br*AW + kw+4+rr];
                    mma_bf16(c4[nn], ah0, ah1, ah2, ah3, bh0, bh1);
                    mma_bf16(c4[nn], ah0, ah1, ah2, ah3, bl0, bl1);
                    mma_bf16(c4[nn], al0, al1, al2, al3, bh0, bh1);
                }
            }
            int krow = warp_m*16 + qq;
#pragma unroll
            for (int nn = 0; nn < 4; nn++) {
                int qc = warp_n*32 + nn*8 + 2*rr;
                STm[ krow   *66 + qc    ] = c4[nn][0];
                STm[ krow   *66 + qc + 1] = c4[nn][1];
                STm[(krow+8)*66 + qc    ] = c4[nn][2];
                STm[(krow+8)*66 + qc + 1] = c4[nn][3];
            }
        }
        uint2 vh[4], vl[4];
#pragma unroll
        for (int i = 0; i < 4; i++) {
            int d = ty + 16*i;
            size_t gi = baseVT + (size_t)d * SS + k0 + 4*tx;
            vh[i] = *(const uint2*)(gb_v_h + gi);
            vl[i] = *(const uint2*)(gb_v_l + gi);
        }
        __syncthreads();

        // online softmax
        {
            int row = t >> 2, sub = t & 3;
            int qglob = q0 + row;
            float mo = m_s[row];
            float mx = mo;
            float ev[16];
#pragma unroll
            for (int j2 = 0; j2 < 16; j2++) {
                int key = sub*16 + j2;
                float sv = STm[key*66 + row] * 0.125f;
                if (k0 + key > qglob) sv = -1.0e30f;
                ev[j2] = sv;
                mx = fmaxf(mx, sv);
            }
            mx = fmaxf(mx, __shfl_xor_sync(0xffffffffu, mx, 1));
            mx = fmaxf(mx, __shfl_xor_sync(0xffffffffu, mx, 2));
            float sum = 0.f;
#pragma unroll
            for (int j2 = 0; j2 < 16; j2++) {
                float e = __expf(ev[j2] - mx);
                ev[j2] = e; sum += e;
            }
#pragma unroll
            for (int j2 = 0; j2 < 8; j2++) {
                unsigned hi, lo;
                split_pack(ev[2*j2], ev[2*j2+1], hi, lo);
                usm[A_PH + row*AW + sub*8 + j2] = hi;
                usm[A_PL + row*AW + sub*8 + j2] = lo;
            }
            sum += __shfl_xor_sync(0xffffffffu, sum, 1);
            sum += __shfl_xor_sync(0xffffffffu, sum, 2);
            if (sub == 0) {
                float alpha = __expf(mo - mx);
                m_s[row] = mx;
                l_s[row] = l_s[row] * alpha + sum;
                al_s[row] = alpha;
            }
        }
#pragma unroll
        for (int i = 0; i < 4; i++) {
            int d = ty + 16*i;
            usm[A_KH + d*AW + 2*tx] = vh[i].x;  usm[A_KH + d*AW + 2*tx + 1] = vh[i].y;
            usm[A_KL + d*AW + 2*tx] = vl[i].x;  usm[A_KL + d*AW + 2*tx + 1] = vl[i].y;
        }
        __syncthreads();

        // O *= alpha ; O += P @ V
        {
            int qr = warp_m*16 + qq;
            float a0 = al_s[qr], a1 = al_s[qr + 8];
#pragma unroll
            for (int nn = 0; nn < 4; nn++) {
                oacc[nn][0] *= a0; oacc[nn][1] *= a0;
                oacc[nn][2] *= a1; oacc[nn][3] *= a1;
            }
#pragma unroll
            for (int ks = 0; ks < 4; ks++) {
                int kw = ks*8;
                int ar = warp_m*16 + qq;
                unsigned ah0 = usm[A_PH +  ar   *AW + kw+rr];
                unsigned ah1 = usm[A_PH + (ar+8)*AW + kw+rr];
                unsigned ah2 = usm[A_PH +  ar   *AW + kw+4+rr];
                unsigned ah3 = usm[A_PH + (ar+8)*AW + kw+4+rr];
                unsigned al0 = usm[A_PL +  ar   *AW + kw+rr];
                unsigned al1 = usm[A_PL + (ar+8)*AW + kw+rr];
                unsigned al2 = usm[A_PL +  ar   *AW + kw+4+rr];
                unsigned al3 = usm[A_PL + (ar+8)*AW + kw+4+rr];
#pragma unroll
                for (int nn = 0; nn < 4; nn++) {
                    int br = warp_n*32 + nn*8 + qq;
                    unsigned bh0 = usm[A_KH + br*AW + kw+rr];
                    unsigned bh1 = usm[A_KH + br*AW + kw+4+rr];
                    unsigned bl0 = usm[A_KL + br*AW + kw+rr];
                    unsigned bl1 = usm[A_KL + br*AW + kw+4+rr];
                    mma_bf16(oacc[nn], ah0, ah1, ah2, ah3, bh0, bh1);
                    mma_bf16(oacc[nn], ah0, ah1, ah2, ah3, bl0, bl1);
                    mma_bf16(oacc[nn], al0, al1, al2, al3, bh0, bh1);
                }
            }
        }
        __syncthreads();
    }

    {
        int qr = warp_m*16 + qq;
        float inv0 = 1.f / l_s[qr];
        float inv1 = 1.f / l_s[qr + 8];
#pragma unroll
        for (int nn = 0; nn < 4; nn++) {
            int dc = warp_n*32 + nn*8 + 2*rr;
            size_t i0 = baseQ + (size_t)(q0 + qr) * DD + dc;
            size_t i1 = baseQ + (size_t)(q0 + qr + 8) * DD + dc;
            split_store(oacc[nn][0] * inv0, gb_attn_h, gb_attn_l, i0);
            split_store(oacc[nn][1] * inv0, gb_attn_h, gb_attn_l, i0+1);
            split_store(oacc[nn][2] * inv1, gb_attn_h, gb_attn_l, i1);
            split_store(oacc[nn][3] * inv1, gb_attn_h, gb_attn_l, i1+1);
        }
    }
}

// ---------------- Predictor (two-stage, parallel, deterministic) ----------
__global__ void pred_partA()
{
    int b = blockIdx.x, ch = blockIdx.y;
    int t = threadIdx.x;
#pragma unroll
    for (int c = 0; c < 4; c++) {
        int col = t + 256*c;
        float s = 0.f;
        const float* p = g_gout + ((size_t)b*SS + ch*64) * DD + col;
        for (int r = 0; r < 64; r++) s += p[(size_t)r * DD];
        g_pp[((size_t)b*16 + ch)*DD + col] = s;
    }
}

__global__ void pred_partB(const float* __restrict__ Wp, const float* __restrict__ bp)
{
    __shared__ float red[256];
    int b = blockIdx.x;
    int t = threadIdx.x;
    float part = 0.f;
#pragma unroll
    for (int c = 0; c < 4; c++) {
        int col = t + 256*c;
        float s = 0.f;
#pragma unroll
        for (int ch = 0; ch < 16; ch++)
            s += g_pp[((size_t)b*16 + ch)*DD + col];
        part += (s * (1.0f/SS)) * Wp[col];
    }
    red[t] = part; __syncthreads();
    for (int o = 128; o > 0; o >>= 1) { if (t < o) red[t] += red[t+o]; __syncthreads(); }
    if (t == 0) {
        float z = red[0] + bp[0];
        g_base[b] = 1.f / (1.f + expf(-z));
    }
}

// ---------------- Span params ----------------
__global__ void params_kernel()
{
    float smf = (g_base[0] + g_base[1] + g_base[2] + g_base[3]) * 0.25f;
    double sm = (double)smf;
    int win = (int)(256.0 * sm);      if (win < 1) win = 1;
    int span_len = (int)(512.0 * sm); if (span_len < 1) span_len = 1;
    int lm = 512;
    if (span_len < lm) lm = span_len;
    if (win < lm) lm = win;
    g_params.win = win;
    g_params.span_len = span_len;
    g_params.local_max = lm;
    g_params.span_mean = smf;
    g_params.temp = (float)(1.0 + 0.01 * (1.0 - sm));
}

// ---------------- Local span attention (K == V); zero-fills [eff, wlen) ---
__global__ void __launch_bounds__(256) attn_local_kernel()
{
    __shared__ float Qs[32][65];
    __shared__ float Ks[64][65];
    __shared__ float Ss[32][65];
    __shared__ float m_s[32], l_s[32], alpha_s[32];

    SpanParams p = g_params;
    int bh = blockIdx.x;  int b = bh >> 4, h = bh & 15;
    int qt = blockIdx.y;
    int t = threadIdx.x;
    int tx = t & 15, ty = t >> 4;
    size_t base = (size_t)b * SS * DD + h * HD;
    float sc = 0.35355339059327373f / p.temp;

    for (int w = blockIdx.z; w * p.win < SS; w += (int)gridDim.z) {
        int st = w * p.win;
        int en = st + p.win; if (en > SS) en = SS;
        int wlen = en - st;
        int ks0 = st - p.span_len + p.win; if (ks0 < 0) ks0 = 0;
        int ke = st + p.span_len; if (ke > SS) ke = SS;
        int klen = ke - ks0;
        int eff = (int)((double)wlen * (double)p.span_mean);
        if (eff > wlen) eff = wlen;
        if (eff > klen) eff = klen;
        if (eff > p.local_max) eff = p.local_max;
        int q0 = qt * 32;
        if (q0 >= wlen) continue;
        bool docompute = (eff > 0 && q0 < eff);
        int qcnt = 0;
        if (docompute) { qcnt = eff - q0; if (qcnt > 32) qcnt = 32; }

        float accO[2][4];
#pragma unroll
        for (int i = 0; i < 2; i++)
#pragma unroll
            for (int j = 0; j < 4; j++) accO[i][j] = 0.f;

        if (docompute) {
            {
                int col = tx * 4;
#pragma unroll
                for (int rr2 = 0; rr2 < 2; rr2++) {
                    int r = ty + rr2*16;
                    float4 qv = make_float4(0.f,0.f,0.f,0.f);
                    if (r < qcnt)
                        qv = *(const float4*)(g_local + base + (size_t)(st + q0 + r) * DD + col);
                    Qs[r][col+0]=qv.x; Qs[r][col+1]=qv.y; Qs[r][col+2]=qv.z; Qs[r][col+3]=qv.w;
                }
            }
            if (t < 32) { m_s[t] = -3.0e38f; l_s[t] = 0.f; }
            __syncthreads();

            int nkt = (eff + 63) >> 6;
            for (int kt = 0; kt < nkt; kt++) {
                {
                    int col = tx * 4;
#pragma unroll
                    for (int rr2 = 0; rr2 < 4; rr2++) {
                        int r = ty + rr2*16;
                        float4 kv = make_float4(0.f,0.f,0.f,0.f);
                        if (kt*64 + r < eff)
                            kv = *(const float4*)(g_local + base + (size_t)(ks0 + kt*64 + r) * DD + col);
                        Ks[r][col+0]=kv.x; Ks[r][col+1]=kv.y; Ks[r][col+2]=kv.z; Ks[r][col+3]=kv.w;
                    }
                }
                __syncthreads();
                float sacc[2][4];
#pragma unroll
                for (int i = 0; i < 2; i++)
#pragma unroll
                    for (int j = 0; j < 4; j++) sacc[i][j] = 0.f;
#pragma unroll 8
                for (int kk = 0; kk < 64; kk++) {
                    float qv0 = Qs[2*ty+0][kk];
                    float qv1 = Qs[2*ty+1][kk];
#pragma unroll
                    for (int j = 0; j < 4; j++) {
                        float kv = Ks[4*tx+j][kk];
                        sacc[0][j] += qv0*kv;
                        sacc[1][j] += qv1*kv;
                    }
                }
#pragma unroll
                for (int i = 0; i < 2; i++) {
#pragma unroll
                    for (int j = 0; j < 4; j++) {
                        float sv = sacc[i][j] * sc;
                        if (kt*64 + 4*tx + j >= eff) sv = -1.0e30f;
                        Ss[2*ty+i][4*tx+j] = sv;
                    }
                }
                __syncthreads();
                {
                    int row = t >> 3, sub = t & 7;
                    float mo = m_s[row];
                    float mx = mo;
#pragma unroll
                    for (int c = sub; c < 64; c += 8) mx = fmaxf(mx, Ss[row][c]);
                    mx = fmaxf(mx, __shfl_xor_sync(0xffffffffu, mx, 1));
                    mx = fmaxf(mx, __shfl_xor_sync(0xffffffffu, mx, 2));
                    mx = fmaxf(mx, __shfl_xor_sync(0xffffffffu, mx, 4));
                    float sum = 0.f;
#pragma unroll
                    for (int c = sub; c < 64; c += 8) {
                        float e = __expf(Ss[row][c] - mx);
                        Ss[row][c] = e; sum += e;
                    }
                    sum += __shfl_xor_sync(0xffffffffu, sum, 1);
                    sum += __shfl_xor_sync(0xffffffffu, sum, 2);
                    sum += __shfl_xor_sync(0xffffffffu, sum, 4);
                    if (sub == 0) {
                        float alpha = __expf(mo - mx);
                        m_s[row] = mx;
                        l_s[row] = l_s[row]*alpha + sum;
                        alpha_s[row] = alpha;
                    }
                }
                __syncthreads();
#pragma unroll
                for (int i = 0; i < 2; i++) {
                    float al = alpha_s[2*ty+i];
#pragma unroll
                    for (int j = 0; j < 4; j++) accO[i][j] *= al;
                }
#pragma unroll 4
                for (int c = 0; c < 64; c++) {
                    float p0 = Ss[2*ty+0][c];
                    float p1 = Ss[2*ty+1][c];
#pragma unroll
                    for (int j = 0; j < 4; j++) {
                        float vv = Ks[c][4*tx+j];
                        accO[0][j] += p0*vv;
                        accO[1][j] += p1*vv;
                    }
                }
                __syncthreads();
            }
        }

        // store: attention rows [0, qcnt), zeros for rows [qcnt, wlen-q0)
#pragma unroll
        for (int i = 0; i < 2; i++) {
            int rloc = 2*ty + i;
            if (q0 + rloc >= wlen) continue;
            size_t idx = base + (size_t)(st + q0 + rloc) * DD + 4*tx;
            if (rloc < qcnt) {
                float inv = 1.f / l_s[rloc];
#pragma unroll
                for (int j = 0; j < 4; j++)
                    split_store(accO[i][j] * inv, gb_lout_h, gb_lout_l, idx + j);
            } else {
                *(uint2*)(gb_lout_h + idx) = make_uint2(0u, 0u);
                *(uint2*)(gb_lout_l + idx) = make_uint2(0u, 0u);
            }
        }
        __syncthreads();
    }
}

// ---------------- launch ----------------
extern "C" void kernel_launch(void* const* d_in, const int* in_sizes, int n_in,
                              void* d_out, int out_size)
{
    const float* x     = (const float*)d_in[0];
    const float* ln_ag = (const float*)d_in[1];
    const float* ln_ab = (const float*)d_in[2];
    const float* ln_bg = (const float*)d_in[3];
    const float* ln_bb = (const float*)d_in[4];
    const float* Wq    = (const float*)d_in[5];
    const float* bq    = (const float*)d_in[6];
    const float* Wk    = (const float*)d_in[7];
    const float* Wv    = (const float*)d_in[8];
    const float* bv    = (const float*)d_in[9];
    const float* Wo    = (const float*)d_in[10];
    const float* bo    = (const float*)d_in[11];
    const float* Wp    = (const float*)d_in[12];
    const float* bp    = (const float*)d_in[13];
    const float* Wproj = (const float*)d_in[14];
    const float* bproj = (const float*)d_in[15];
    float* out = (float*)d_out;

    void *p_gout, *p_lh, *p_ll;
    void *p_gh, *p_gl, *p_qh, *p_ql, *p_kh, *p_kl, *p_vh, *p_vl;
    void *p_ah, *p_al, *p_oh, *p_ol;
    void *p_wqh, *p_wql, *p_wkh, *p_wkl, *p_wvh, *p_wvl, *p_woh, *p_wol, *p_wph, *p_wpl;
    cudaGetSymbolAddress(&p_gout, g_gout);
    cudaGetSymbolAddress(&p_lh, gb_lout_h);  cudaGetSymbolAddress(&p_ll, gb_lout_l);
    cudaGetSymbolAddress(&p_gh, gb_globe_h); cudaGetSymbolAddress(&p_gl, gb_globe_l);
    cudaGetSymbolAddress(&p_qh, gb_q_h);     cudaGetSymbolAddress(&p_ql, gb_q_l);
    cudaGetSymbolAddress(&p_kh, gb_k_h);     cudaGetSymbolAddress(&p_kl, gb_k_l);
    cudaGetSymbolAddress(&p_vh, gb_v_h);     cudaGetSymbolAddress(&p_vl, gb_v_l);
    cudaGetSymbolAddress(&p_ah, gb_attn_h);  cudaGetSymbolAddress(&p_al, gb_attn_l);
    cudaGetSymbolAddress(&p_oh, gb_gout_h);  cudaGetSymbolAddress(&p_ol, gb_gout_l);
    cudaGetSymbolAddress(&p_wqh, gb_wq_h);   cudaGetSymbolAddress(&p_wql, gb_wq_l);
    cudaGetSymbolAddress(&p_wkh, gb_wk_h);   cudaGetSymbolAddress(&p_wkl, gb_wk_l);
    cudaGetSymbolAddress(&p_wvh, gb_wv_h);   cudaGetSymbolAddress(&p_wvl, gb_wv_l);
    cudaGetSymbolAddress(&p_woh, gb_wo_h);   cudaGetSymbolAddress(&p_wol, gb_wo_l);
    cudaGetSymbolAddress(&p_wph, gb_wp_h);   cudaGetSymbolAddress(&p_wpl, gb_wp_l);

    cudaFuncSetAttribute(gemm_bf16lm, cudaFuncAttributeMaxDynamicSharedMemorySize, GEMM_SMEM_BYTES);
    cudaFuncSetAttribute(attn_global_mma, cudaFuncAttributeMaxDynamicSharedMemorySize, ATT_SMEM_BYTES);

    // 0) LayerNorms
    ln_kernel<<<MROWS, 256>>>(x, ln_ag, ln_ab, ln_bg, ln_bb);

    // 1) merged weight split (all 5 weights)
    const int NCONV = 4*W1M4 + W2M4;
    conv_split_all<<<(NCONV+255)/256, 256>>>((const float4*)Wq, (const float4*)Wk,
                                             (const float4*)Wv, (const float4*)Wo,
                                             (const float4*)Wproj);

    // 2-4) QKV projections (bf16 hi/lo outputs; V transposed)
    dim3 ggrid(DD/128, MROWS/128);
    gemm_bf16lm<<<ggrid, 256, GEMM_SMEM_BYTES>>>((__nv_bfloat16*)p_gh, (__nv_bfloat16*)p_gl,
        nullptr, nullptr,
        (__nv_bfloat16*)p_wqh, (__nv_bfloat16*)p_wql, bq, nullptr,
        (__nv_bfloat16*)p_qh, (__nv_bfloat16*)p_ql, DD, DD, DD, DD, 0, 32, 0);
    gemm_bf16lm<<<ggrid, 256, GEMM_SMEM_BYTES>>>((__nv_bfloat16*)p_gh, (__nv_bfloat16*)p_gl,
        nullptr, nullptr,
        (__nv_bfloat16*)p_wkh, (__nv_bfloat16*)p_wkl, nullptr, nullptr,
        (__nv_bfloat16*)p_kh, (__nv_bfloat16*)p_kl, DD, DD, DD, DD, 0, 32, 0);
    gemm_bf16lm<<<ggrid, 256, GEMM_SMEM_BYTES>>>((__nv_bfloat16*)p_gh, (__nv_bfloat16*)p_gl,
        nullptr, nullptr,
        (__nv_bfloat16*)p_wvh, (__nv_bfloat16*)p_wvl, bv, nullptr,
        (__nv_bfloat16*)p_vh, (__nv_bfloat16*)p_vl, DD, DD, DD, DD, 0, 32, 1);

    // 5) Global causal attention
    attn_global_mma<<<dim3(16, BB*HH), 256, ATT_SMEM_BYTES>>>();

    // 6) Output projection (fp32 gout for predictor + hi/lo for Wproj)
    gemm_bf16lm<<<ggrid, 256, GEMM_SMEM_BYTES>>>((__nv_bfloat16*)p_ah, (__nv_bfloat16*)p_al,
        nullptr, nullptr,
        (__nv_bfloat16*)p_woh, (__nv_bfloat16*)p_wol, bo, (float*)p_gout,
        (__nv_bfloat16*)p_oh, (__nv_bfloat16*)p_ol, DD, DD, DD, DD, 0, 32, 0);

    // 7-9) Span predictor + params
    pred_partA<<<dim3(BB, 16), 256>>>();
    pred_partB<<<BB, 256>>>(Wp, bp);
    params_kernel<<<1, 1>>>();

    // 10) Local span attention (zero-fills rows [eff, wlen) itself)
    attn_local_kernel<<<dim3(BB*HH, 8, 16), 256>>>();

    // 11) Fused final projection: out = [local_out | globe_out] @ Wproj^T + bproj
    gemm_bf16lm<<<ggrid, 256, GEMM_SMEM_BYTES>>>((__nv_bfloat16*)p_lh, (__nv_bfloat16*)p_ll,
        (__nv_bfloat16*)p_oh, (__nv_bfloat16*)p_ol,
        (__nv_bfloat16*)p_wph, (__nv_bfloat16*)p_wpl, bproj, out,
        nullptr, nullptr, DD, DD, 2*DD, 2*DD, 0, 32, 0);
}

// round 14
// speedup vs baseline: 1.0587x; 1.0587x over previous
#include <cuda_runtime.h>
#include <cuda_bf16.h>
#include <math.h>

#define BB 4
#define SS 1024
#define DD 1024
#define HH 16
#define HD 64
#define MROWS (BB*SS)

// ---------------- scratch (device globals; no allocation) ----------------
__device__ float g_local[MROWS*DD];
__device__ float g_gout[MROWS*DD];
__device__ float g_base[BB];
__device__ float g_pp[BB*16*DD];

// bf16 hi/lo planes
__device__ __nv_bfloat16 gb_globe_h[MROWS*DD], gb_globe_l[MROWS*DD];
__device__ __nv_bfloat16 gb_q_h[MROWS*DD],    gb_q_l[MROWS*DD];
__device__ __nv_bfloat16 gb_k_h[MROWS*DD],    gb_k_l[MROWS*DD];
__device__ __nv_bfloat16 gb_v_h[MROWS*DD],    gb_v_l[MROWS*DD];   // transposed [b][h][d][s]
__device__ __nv_bfloat16 gb_attn_h[MROWS*DD], gb_attn_l[MROWS*DD];
__device__ __nv_bfloat16 gb_gout_h[MROWS*DD], gb_gout_l[MROWS*DD];
__device__ __nv_bfloat16 gb_lout_h[MROWS*DD], gb_lout_l[MROWS*DD];
__device__ __nv_bfloat16 gb_wq_h[DD*DD], gb_wq_l[DD*DD];
__device__ __nv_bfloat16 gb_wk_h[DD*DD], gb_wk_l[DD*DD];
__device__ __nv_bfloat16 gb_wv_h[DD*DD], gb_wv_l[DD*DD];
__device__ __nv_bfloat16 gb_wo_h[DD*DD], gb_wo_l[DD*DD];
__device__ __nv_bfloat16 gb_wp_h[DD*2*DD], gb_wp_l[DD*2*DD];

struct SpanParams {
    int win, span_len, local_max;
    float span_mean, temp;
};
__device__ SpanParams g_params;

// ---------------- helpers ----------------
__device__ __forceinline__ void split_pack(float x0, float x1, unsigned &hi, unsigned &lo)
{
    __nv_bfloat16 h0 = __float2bfloat16(x0);
    __nv_bfloat16 h1 = __float2bfloat16(x1);
    float f0 = __bfloat162float(h0), f1 = __bfloat162float(h1);
    __nv_bfloat16 l0 = __float2bfloat16(x0 - f0);
    __nv_bfloat16 l1 = __float2bfloat16(x1 - f1);
    hi = ((unsigned)__bfloat16_as_ushort(h1) << 16) | (unsigned)__bfloat16_as_ushort(h0);
    lo = ((unsigned)__bfloat16_as_ushort(l1) << 16) | (unsigned)__bfloat16_as_ushort(l0);
}

__device__ __forceinline__ void split_store(float v, __nv_bfloat16* hi, __nv_bfloat16* lo, size_t idx)
{
    __nv_bfloat16 h = __float2bfloat16(v);
    hi[idx] = h;
    lo[idx] = __float2bfloat16(v - __bfloat162float(h));
}

__device__ __forceinline__ void mma_bf16(float c[4],
                                         unsigned a0, unsigned a1, unsigned a2, unsigned a3,
                                         unsigned b0, unsigned b1)
{
    asm volatile("mma.sync.aligned.m16n8k16.row.col.f32.bf16.bf16.f32 "
                 "{%0,%1,%2,%3}, {%4,%5,%6,%7}, {%8,%9}, {%0,%1,%2,%3};"
                 : "+f"(c[0]), "+f"(c[1]), "+f"(c[2]), "+f"(c[3])
                 : "r"(a0), "r"(a1), "r"(a2), "r"(a3), "r"(b0), "r"(b1));
}

__device__ __forceinline__ void ldsm4(unsigned &r0, unsigned &r1, unsigned &r2, unsigned &r3, unsigned addr)
{
    asm volatile("ldmatrix.sync.aligned.m8n8.x4.shared.b16 {%0,%1,%2,%3}, [%4];"
                 : "=r"(r0), "=r"(r1), "=r"(r2), "=r"(r3) : "r"(addr));
}

__device__ __forceinline__ void cpa16(unsigned saddr, const void* g)
{
    asm volatile("cp.async.ca.shared.global [%0], [%1], 16;" :: "r"(saddr), "l"(g));
}

// ---------------- merged weight split (all 5 weights, 1 launch) ----------
#define W1M4 (DD*DD/4)
#define W2M4 (DD*2*DD/4)
__global__ void conv_split_all(const float4* __restrict__ wq, const float4* __restrict__ wk,
                               const float4* __restrict__ wv, const float4* __restrict__ wo,
                               const float4* __restrict__ wp)
{
    int i = blockIdx.x * blockDim.x + threadIdx.x;
    const float4* src;
    __nv_bfloat16 *hi, *lo;
    int off;
    if (i < W1M4)            { src = wq; hi = gb_wq_h; lo = gb_wq_l; off = i; }
    else if (i < 2*W1M4)     { src = wk; hi = gb_wk_h; lo = gb_wk_l; off = i - W1M4; }
    else if (i < 3*W1M4)     { src = wv; hi = gb_wv_h; lo = gb_wv_l; off = i - 2*W1M4; }
    else if (i < 4*W1M4)     { src = wo; hi = gb_wo_h; lo = gb_wo_l; off = i - 3*W1M4; }
    else if (i < 4*W1M4+W2M4){ src = wp; hi = gb_wp_h; lo = gb_wp_l; off = i - 4*W1M4; }
    else return;
    float4 v = src[off];
    unsigned h0, l0, h1, l1;
    split_pack(v.x, v.y, h0, l0);
    split_pack(v.z, v.w, h1, l1);
    *(uint2*)(hi + (size_t)off*4) = make_uint2(h0, h1);
    *(uint2*)(lo + (size_t)off*4) = make_uint2(l0, l1);
}

// ---------------- LayerNorm: fp32 local + bf16 hi/lo globe ----------------
__global__ void ln_kernel(const float* __restrict__ x,
                          const float* __restrict__ ga, const float* __restrict__ ba,
                          const float* __restrict__ gb, const float* __restrict__ bb)
{
    __shared__ float red[256];
    int row = blockIdx.x;
    int t = threadIdx.x;
    const float* xr = x + (size_t)row * DD;
    float v[4];
    float s = 0.f;
#pragma unroll
    for (int k = 0; k < 4; k++) { v[k] = xr[t + 256*k]; s += v[k]; }
    red[t] = s; __syncthreads();
    for (int o = 128; o > 0; o >>= 1) { if (t < o) red[t] += red[t+o]; __syncthreads(); }
    float mean = red[0] * (1.0f/DD);
    __syncthreads();
    float s2 = 0.f;
#pragma unroll
    for (int k = 0; k < 4; k++) { float d0 = v[k]-mean; s2 += d0*d0; }
    red[t] = s2; __syncthreads();
    for (int o = 128; o > 0; o >>= 1) { if (t < o) red[t] += red[t+o]; __syncthreads(); }
    float rs = rsqrtf(red[0]*(1.0f/DD) + 1e-5f);
#pragma unroll
    for (int k = 0; k < 4; k++) {
        int c = t + 256*k;
        float nh = (v[k]-mean)*rs;
        size_t idx = (size_t)row*DD + c;
        g_local[idx] = nh*ga[c] + ba[c];
        split_store(nh*gb[c] + bb[c], gb_globe_h, gb_globe_l, idx);
    }
}

// ---------------- bf16x3 GEMM: cp.async + ldmatrix, double-buffered -------
// (R12-measured best configuration: 80B rows, 2-stage, .ca, dual-A fusion)
#define GSM_ROWB 80
#define GSM_PLANE 10240
#define GSM_BUF 40960
#define GEMM_SMEM_BYTES (2*GSM_BUF)

__global__ void __launch_bounds__(256, 2) gemm_bf16lm(
    const __nv_bfloat16* __restrict__ Ah, const __nv_bfloat16* __restrict__ Al,
    const __nv_bfloat16* __restrict__ A2h, const __nv_bfloat16* __restrict__ A2l,
    const __nv_bfloat16* __restrict__ Wh, const __nv_bfloat16* __restrict__ Wl,
    const float* __restrict__ bias, float* __restrict__ C,
    __nv_bfloat16* __restrict__ Chi, __nv_bfloat16* __restrict__ Clo,
    int N, int lda, int K, int ldw, int koff, int k1ch, int transv)
{
    extern __shared__ char sm8[];
    unsigned sbase = (unsigned)__cvta_generic_to_shared(sm8);

    int t = threadIdx.x;
    int wid = t >> 5, lane = t & 31;
    int warp_m = wid >> 2, warp_n = wid & 3;
    int bm = blockIdx.y * 128, bn = blockIdx.x * 128;
    int qq = lane >> 2, rr = lane & 3;

    int crow = t >> 1;
    int csp = t & 1;
    const __nv_bfloat16* gAh = Ah + (size_t)(bm + crow) * lda + csp*16;
    const __nv_bfloat16* gAl = Al + (size_t)(bm + crow) * lda + csp*16;
    const __nv_bfloat16* gA2h = A2h ? A2h + (size_t)(bm + crow) * lda + csp*16 : gAh;
    const __nv_bfloat16* gA2l = A2l ? A2l + (size_t)(bm + crow) * lda + csp*16 : gAl;
    const __nv_bfloat16* gWh = Wh + (size_t)(bn + crow) * ldw + koff + csp*16;
    const __nv_bfloat16* gWl = Wl + (size_t)(bn + crow) * ldw + koff + csp*16;
    unsigned dOff = crow*GSM_ROWB + csp*32;

    int mq = lane >> 3, j = lane & 7;
    unsigned aoff = (warp_m*64 + (mq&1)*8 + j)*GSM_ROWB + (mq>>1)*16;
    unsigned boff = (warp_n*32 + (mq>>1)*8 + j)*GSM_ROWB + (mq&1)*16;

    float acc[4][4][4];
#pragma unroll
    for (int im = 0; im < 4; im++)
#pragma unroll
        for (int in = 0; in < 4; in++)
#pragma unroll
            for (int r = 0; r < 4; r++) acc[im][in][r] = 0.f;

#define ISSUE(buf, kc) do { \
    unsigned d = sbase + (buf)*GSM_BUF + dOff; \
    const __nv_bfloat16* sh_ = ((kc) < k1ch) ? gAh + (size_t)(kc)*32 : gA2h + (size_t)((kc) - k1ch)*32; \
    const __nv_bfloat16* sl_ = ((kc) < k1ch) ? gAl + (size_t)(kc)*32 : gA2l + (size_t)((kc) - k1ch)*32; \
    cpa16(d,                   sh_); \
    cpa16(d+16,                sh_ + 8); \
    cpa16(d+GSM_PLANE,         sl_); \
    cpa16(d+GSM_PLANE+16,      sl_ + 8); \
    cpa16(d+2*GSM_PLANE,       gWh + (size_t)(kc)*32); \
    cpa16(d+2*GSM_PLANE+16,    gWh + (size_t)(kc)*32 + 8); \
    cpa16(d+3*GSM_PLANE,       gWl + (size_t)(kc)*32); \
    cpa16(d+3*GSM_PLANE+16,    gWl + (size_t)(kc)*32 + 8); \
    asm volatile("cp.async.commit_group;"); \
} while (0)

    int nch = K / 32;
    ISSUE(0, 0);
    if (nch > 1) ISSUE(1, 1);

    for (int c = 0; c < nch; c++) {
        int cur = c & 1;
        if (c + 1 < nch) asm volatile("cp.async.wait_group 1;");
        else             asm volatile("cp.async.wait_group 0;");
        __syncthreads();

        unsigned pah = sbase + cur*GSM_BUF + aoff;
        unsigned pal = pah + GSM_PLANE;
        unsigned pbh = sbase + cur*GSM_BUF + 2*GSM_PLANE + boff;
        unsigned pbl = pbh + GSM_PLANE;
#pragma unroll
        for (int ks = 0; ks < 2; ks++) {
            unsigned kb = ks*32;
            unsigned bh0[4], bh1[4], bl0[4], bl1[4];
            {
                unsigned r0,r1,r2,r3;
                ldsm4(r0,r1,r2,r3, pbh + kb);
                bh0[0]=r0; bh1[0]=r1; bh0[1]=r2; bh1[1]=r3;
                ldsm4(r0,r1,r2,r3, pbh + 1280 + kb);
                bh0[2]=r0; bh1[2]=r1; bh0[3]=r2; bh1[3]=r3;
                ldsm4(r0,r1,r2,r3, pbl + kb);
                bl0[0]=r0; bl1[0]=r1; bl0[1]=r2; bl1[1]=r3;
                ldsm4(r0,r1,r2,r3, pbl + 1280 + kb);
                bl0[2]=r0; bl1[2]=r1; bl0[3]=r2; bl1[3]=r3;
            }
#pragma unroll
            for (int im = 0; im < 4; im++) {
                unsigned ah0,ah1,ah2,ah3, al0,al1,al2,al3;
                ldsm4(ah0,ah1,ah2,ah3, pah + im*1280 + kb);
                ldsm4(al0,al1,al2,al3, pal + im*1280 + kb);
#pragma unroll
                for (int in = 0; in < 4; in++) {
                    mma_bf16(acc[im][in], ah0,ah1,ah2,ah3, bh0[in], bh1[in]);
                    mma_bf16(acc[im][in], ah0,ah1,ah2,ah3, bl0[in], bl1[in]);
                    mma_bf16(acc[im][in], al0,al1,al2,al3, bh0[in], bh1[in]);
                }
            }
        }
        __syncthreads();
        if (c + 2 < nch) ISSUE(cur, c + 2);
    }
#undef ISSUE

    // epilogue
#pragma unroll
    for (int im = 0; im < 4; im++) {
        int r0 = bm + warp_m*64 + im*16 + qq;
#pragma unroll
        for (int in = 0; in < 4; in++) {
            int c0 = bn + warp_n*32 + in*8 + 2*rr;
            float b0v = bias ? bias[c0]   : 0.f;
            float b1v = bias ? bias[c0+1] : 0.f;
#pragma unroll
            for (int half = 0; half < 2; half++) {
                int m = r0 + half*8;
                float v0 = acc[im][in][2*half + 0] + b0v;
                float v1 = acc[im][in][2*half + 1] + b1v;
                if (transv) {
                    size_t i0 = ((size_t)((m>>10)*HH + (c0>>6))*HD + (c0&63))*SS + (m&1023);
                    size_t i1 = ((size_t)((m>>10)*HH + ((c0+1)>>6))*HD + ((c0+1)&63))*SS + (m&1023);
                    split_store(v0, Chi, Clo, i0);
                    split_store(v1, Chi, Clo, i1);
                } else {
                    size_t idx = (size_t)m * N + c0;
                    if (C) { C[idx] = v0; C[idx+1] = v1; }
                    if (Chi) {
                        split_store(v0, Chi, Clo, idx);
                        split_store(v1, Chi, Clo, idx+1);
                    }
                }
            }
        }
    }
}

// ---------------- Global causal attention (bf16x3 MMA, K-tile prefetch) ---
#define AW 36
#define A_QH 0
#define A_QL 2304
#define A_KH 4608
#define A_KL 6912
#define A_PH 9216
#define A_PL 11520
#define A_ST 13824               // float [64][66]
#define A_MS (13824 + 4224)
#define ATT_SMEM_WORDS (13824 + 4224 + 192)
#define ATT_SMEM_BYTES (ATT_SMEM_WORDS*4)

__global__ void __launch_bounds__(256, 2) attn_global_mma()
{
    extern __shared__ unsigned usm[];
    float* STm = (float*)(usm + A_ST);
    float* m_s = (float*)(usm + A_MS);
    float* l_s = m_s + 64;
    float* al_s = l_s + 64;

    int qt = 15 - (int)blockIdx.x;
    int bh = blockIdx.y;
    int b = bh >> 4, h = bh & 15;
    int t = threadIdx.x;
    int lane = t & 31, wid = t >> 5;
    int tx = t & 15, ty = t >> 4;
    int warp_m = wid & 3, warp_n = wid >> 2;
    int qq = lane >> 2, rr = lane & 3;
    int q0 = qt * 64;
    size_t baseQ = (size_t)b * SS * DD + h * HD;
    size_t baseVT = ((size_t)(b*HH + h)) * HD * SS;

    // load Q tile hi/lo
#pragma unroll
    for (int i = 0; i < 4; i++) {
        int r = ty + 16*i;
        size_t gi = baseQ + (size_t)(q0 + r) * DD + 4*tx;
        uint2 vh = *(const uint2*)(gb_q_h + gi);
        uint2 vl = *(const uint2*)(gb_q_l + gi);
        usm[A_QH + r*AW + 2*tx] = vh.x;  usm[A_QH + r*AW + 2*tx + 1] = vh.y;
        usm[A_QL + r*AW + 2*tx] = vl.x;  usm[A_QL + r*AW + 2*tx + 1] = vl.y;
    }
    if (t < 64) { m_s[t] = -3.0e38f; l_s[t] = 0.f; }

    float oacc[4][4];
#pragma unroll
    for (int nn = 0; nn < 4; nn++)
#pragma unroll
        for (int r = 0; r < 4; r++) oacc[nn][r] = 0.f;

    // prefetch K tile for kt = 0 into registers
    uint2 kvh[4], kvl[4];
#pragma unroll
    for (int i = 0; i < 4; i++) {
        int r = ty + 16*i;
        size_t gi = baseQ + (size_t)r * DD + 4*tx;
        kvh[i] = *(const uint2*)(gb_k_h + gi);
        kvl[i] = *(const uint2*)(gb_k_l + gi);
    }

    __syncthreads();

    for (int kt = 0; kt <= qt; kt++) {
        int k0 = kt * 64;
        // 1) store prefetched K tile to smem (no exposed global latency)
#pragma unroll
        for (int i = 0; i < 4; i++) {
            int r = ty + 16*i;
            usm[A_KH + r*AW + 2*tx] = kvh[i].x;  usm[A_KH + r*AW + 2*tx + 1] = kvh[i].y;
            usm[A_KL + r*AW + 2*tx] = kvl[i].x;  usm[A_KL + r*AW + 2*tx + 1] = kvl[i].y;
        }
        __syncthreads();

        // 2) S^T = K @ Q^T
        {
            float c4[4][4];
#pragma unroll
            for (int nn = 0; nn < 4; nn++)
#pragma unroll
                for (int r = 0; r < 4; r++) c4[nn][r] = 0.f;
#pragma unroll
            for (int ks = 0; ks < 4; ks++) {
                int kw = ks*8;
                int ar = warp_m*16 + qq;
                unsigned ah0 = usm[A_KH +  ar   *AW + kw+rr];
                unsigned ah1 = usm[A_KH + (ar+8)*AW + kw+rr];
                unsigned ah2 = usm[A_KH +  ar   *AW + kw+4+rr];
                unsigned ah3 = usm[A_KH + (ar+8)*AW + kw+4+rr];
                unsigned al0 = usm[A_KL +  ar   *AW + kw+rr];
                unsigned al1 = usm[A_KL + (ar+8)*AW + kw+rr];
                unsigned al2 = usm[A_KL +  ar   *AW + kw+4+rr];
                unsigned al3 = usm[A_KL + (ar+8)*AW + kw+4+rr];
#pragma unroll
                for (int nn = 0; nn < 4; nn++) {
                    int br = warp_n*32 + nn*8 + qq;
                    unsigned bh0 = usm[A_QH + br*AW + kw+rr];
                    unsigned bh1 = usm[A_QH + br*AW + kw+4+rr];
                    unsigned bl0 = usm[A_QL + br*AW + kw+rr];
                    unsigned bl1 = usm[A_QL + br*AW + kw+4+rr];
                    mma_bf16(c4[nn], ah0, ah1, ah2, ah3, bh0, bh1);
                    mma_bf16(c4[nn], ah0, ah1, ah2, ah3, bl0, bl1);
                    mma_bf16(c4[nn], al0, al1, al2, al3, bh0, bh1);
                }
            }
            int krow = warp_m*16 + qq;
#pragma unroll
            for (int nn = 0; nn < 4; nn++) {
                int qc = warp_n*32 + nn*8 + 2*rr;
                STm[ krow   *66 + qc    ] = c4[nn][0];
                STm[ krow   *66 + qc + 1] = c4[nn][1];
                STm[(krow+8)*66 + qc    ] = c4[nn][2];
                STm[(krow+8)*66 + qc + 1] = c4[nn][3];
            }
        }
        // 3) issue V(kt) loads and K(kt+1) prefetch (latency hidden by softmax)
        uint2 vvh[4], vvl[4];
#pragma unroll
        for (int i = 0; i < 4; i++) {
            int d = ty + 16*i;
            size_t gi = baseVT + (size_t)d * SS + k0 + 4*tx;
            vvh[i] = *(const uint2*)(gb_v_h + gi);
            vvl[i] = *(const uint2*)(gb_v_l + gi);
        }
        if (kt < qt) {
#pragma unroll
            for (int i = 0; i < 4; i++) {
                int r = ty + 16*i;
                size_t gi = baseQ + (size_t)(k0 + 64 + r) * DD + 4*tx;
                kvh[i] = *(const uint2*)(gb_k_h + gi);
                kvl[i] = *(const uint2*)(gb_k_l + gi);
            }
        }
        __syncthreads();

        // 4) online softmax
        {
            int row = t >> 2, sub = t & 3;
            int qglob = q0 + row;
            float mo = m_s[row];
            float mx = mo;
            float ev[16];
#pragma unroll
            for (int j2 = 0; j2 < 16; j2++) {
                int key = sub*16 + j2;
                float sv = STm[key*66 + row] * 0.125f;
                if (k0 + key > qglob) sv = -1.0e30f;
                ev[j2] = sv;
                mx = fmaxf(mx, sv);
            }
            mx = fmaxf(mx, __shfl_xor_sync(0xffffffffu, mx, 1));
            mx = fmaxf(mx, __shfl_xor_sync(0xffffffffu, mx, 2));
            float sum = 0.f;
#pragma unroll
            for (int j2 = 0; j2 < 16; j2++) {
                float e = __expf(ev[j2] - mx);
                ev[j2] = e; sum += e;
            }
#pragma unroll
            for (int j2 = 0; j2 < 8; j2++) {
                unsigned hi, lo;
                split_pack(ev[2*j2], ev[2*j2+1], hi, lo);
                usm[A_PH + row*AW + sub*8 + j2] = hi;
                usm[A_PL + row*AW + sub*8 + j2] = lo;
            }
            sum += __shfl_xor_sync(0xffffffffu, sum, 1);
            sum += __shfl_xor_sync(0xffffffffu, sum, 2);
            if (sub == 0) {
                float alpha = __expf(mo - mx);
                m_s[row] = mx;
                l_s[row] = l_s[row] * alpha + sum;
                al_s[row] = alpha;
            }
        }
        // 5) store V tile into KH/KL
#pragma unroll
        for (int i = 0; i < 4; i++) {
            int d = ty + 16*i;
            usm[A_KH + d*AW + 2*tx] = vvh[i].x;  usm[A_KH + d*AW + 2*tx + 1] = vvh[i].y;
            usm[A_KL + d*AW + 2*tx] = vvl[i].x;  usm[A_KL + d*AW + 2*tx + 1] = vvl[i].y;
        }
        __syncthreads();

        // 6) O *= alpha ; O += P @ V
        {
            int qr = warp_m*16 + qq;
            float a0 = al_s[qr], a1 = al_s[qr + 8];
#pragma unroll
            for (int nn = 0; nn < 4; nn++) {
                oacc[nn][0] *= a0; oacc[nn][1] *= a0;
                oacc[nn][2] *= a1; oacc[nn][3] *= a1;
            }
#pragma unroll
            for (int ks = 0; ks < 4; ks++) {
                int kw = ks*8;
                int ar = warp_m*16 + qq;
                unsigned ah0 = usm[A_PH +  ar   *AW + kw+rr];
                unsigned ah1 = usm[A_PH + (ar+8)*AW + kw+rr];
                unsigned ah2 = usm[A_PH +  ar   *AW + kw+4+rr];
                unsigned ah3 = usm[A_PH + (ar+8)*AW + kw+4+rr];
                unsigned al0 = usm[A_PL +  ar   *AW + kw+rr];
                unsigned al1 = usm[A_PL + (ar+8)*AW + kw+rr];
                unsigned al2 = usm[A_PL +  ar   *AW + kw+4+rr];
                unsigned al3 = usm[A_PL + (ar+8)*AW + kw+4+rr];
#pragma unroll
                for (int nn = 0; nn < 4; nn++) {
                    int br = warp_n*32 + nn*8 + qq;
                    unsigned bh0 = usm[A_KH + br*AW + kw+rr];
                    unsigned bh1 = usm[A_KH + br*AW + kw+4+rr];
                    unsigned bl0 = usm[A_KL + br*AW + kw+rr];
                    unsigned bl1 = usm[A_KL + br*AW + kw+4+rr];
                    mma_bf16(oacc[nn], ah0, ah1, ah2, ah3, bh0, bh1);
                    mma_bf16(oacc[nn], ah0, ah1, ah2, ah3, bl0, bl1);
                    mma_bf16(oacc[nn], al0, al1, al2, al3, bh0, bh1);
                }
            }
        }
        __syncthreads();
    }

    // write O hi/lo (normalized)
    {
        int qr = warp_m*16 + qq;
        float inv0 = 1.f / l_s[qr];
        float inv1 = 1.f / l_s[qr + 8];
#pragma unroll
        for (int nn = 0; nn < 4; nn++) {
            int dc = warp_n*32 + nn*8 + 2*rr;
            size_t i0 = baseQ + (size_t)(q0 + qr) * DD + dc;
            size_t i1 = baseQ + (size_t)(q0 + qr + 8) * DD + dc;
            split_store(oacc[nn][0] * inv0, gb_attn_h, gb_attn_l, i0);
            split_store(oacc[nn][1] * inv0, gb_attn_h, gb_attn_l, i0+1);
            split_store(oacc[nn][2] * inv1, gb_attn_h, gb_attn_l, i1);
            split_store(oacc[nn][3] * inv1, gb_attn_h, gb_attn_l, i1+1);
        }
    }
}

// ---------------- Predictor (two-stage, parallel, deterministic) ----------
__global__ void pred_partA()
{
    int b = blockIdx.x, ch = blockIdx.y;
    int t = threadIdx.x;
#pragma unroll
    for (int c = 0; c < 4; c++) {
        int col = t + 256*c;
        float s = 0.f;
        const float* p = g_gout + ((size_t)b*SS + ch*64) * DD + col;
        for (int r = 0; r < 64; r++) s += p[(size_t)r * DD];
        g_pp[((size_t)b*16 + ch)*DD + col] = s;
    }
}

__global__ void pred_partB(const float* __restrict__ Wp, const float* __restrict__ bp)
{
    __shared__ float red[256];
    int b = blockIdx.x;
    int t = threadIdx.x;
    float part = 0.f;
#pragma unroll
    for (int c = 0; c < 4; c++) {
        int col = t + 256*c;
        float s = 0.f;
#pragma unroll
        for (int ch = 0; ch < 16; ch++)
            s += g_pp[((size_t)b*16 + ch)*DD + col];
        part += (s * (1.0f/SS)) * Wp[col];
    }
    red[t] = part; __syncthreads();
    for (int o = 128; o > 0; o >>= 1) { if (t < o) red[t] += red[t+o]; __syncthreads(); }
    if (t == 0) {
        float z = red[0] + bp[0];
        g_base[b] = 1.f / (1.f + expf(-z));
    }
}

// ---------------- Span params ----------------
__global__ void params_kernel()
{
    float smf = (g_base[0] + g_base[1] + g_base[2] + g_base[3]) * 0.25f;
    double sm = (double)smf;
    int win = (int)(256.0 * sm);      if (win < 1) win = 1;
    int span_len = (int)(512.0 * sm); if (span_len < 1) span_len = 1;
    int lm = 512;
    if (span_len < lm) lm = span_len;
    if (win < lm) lm = win;
    g_params.win = win;
    g_params.span_len = span_len;
    g_params.local_max = lm;
    g_params.span_mean = smf;
    g_params.temp = (float)(1.0 + 0.01 * (1.0 - sm));
}

// ---------------- Local span attention (K == V); zero-fills [eff, wlen) ---
__global__ void __launch_bounds__(256) attn_local_kernel()
{
    __shared__ float Qs[32][65];
    __shared__ float Ks[64][65];
    __shared__ float Ss[32][65];
    __shared__ float m_s[32], l_s[32], alpha_s[32];

    SpanParams p = g_params;
    int bh = blockIdx.x;  int b = bh >> 4, h = bh & 15;
    int qt = blockIdx.y;
    int t = threadIdx.x;
    int tx = t & 15, ty = t >> 4;
    size_t base = (size_t)b * SS * DD + h * HD;
    float sc = 0.35355339059327373f / p.temp;

    for (int w = blockIdx.z; w * p.win < SS; w += (int)gridDim.z) {
        int st = w * p.win;
        int en = st + p.win; if (en > SS) en = SS;
        int wlen = en - st;
        int ks0 = st - p.span_len + p.win; if (ks0 < 0) ks0 = 0;
        int ke = st + p.span_len; if (ke > SS) ke = SS;
        int klen = ke - ks0;
        int eff = (int)((double)wlen * (double)p.span_mean);
        if (eff > wlen) eff = wlen;
        if (eff > klen) eff = klen;
        if (eff > p.local_max) eff = p.local_max;
        int q0 = qt * 32;
        if (q0 >= wlen) continue;
        bool docompute = (eff > 0 && q0 < eff);
        int qcnt = 0;
        if (docompute) { qcnt = eff - q0; if (qcnt > 32) qcnt = 32; }

        float accO[2][4];
#pragma unroll
        for (int i = 0; i < 2; i++)
#pragma unroll
            for (int j = 0; j < 4; j++) accO[i][j] = 0.f;

        if (docompute) {
            {
                int col = tx * 4;
#pragma unroll
                for (int rr2 = 0; rr2 < 2; rr2++) {
                    int r = ty + rr2*16;
                    float4 qv = make_float4(0.f,0.f,0.f,0.f);
                    if (r < qcnt)
                        qv = *(const float4*)(g_local + base + (size_t)(st + q0 + r) * DD + col);
                    Qs[r][col+0]=qv.x; Qs[r][col+1]=qv.y; Qs[r][col+2]=qv.z; Qs[r][col+3]=qv.w;
                }
            }
            if (t < 32) { m_s[t] = -3.0e38f; l_s[t] = 0.f; }
            __syncthreads();

            int nkt = (eff + 63) >> 6;
            for (int kt = 0; kt < nkt; kt++) {
                {
                    int col = tx * 4;
#pragma unroll
                    for (int rr2 = 0; rr2 < 4; rr2++) {
                        int r = ty + rr2*16;
                        float4 kv = make_float4(0.f,0.f,0.f,0.f);
                        if (kt*64 + r < eff)
                            kv = *(const float4*)(g_local + base + (size_t)(ks0 + kt*64 + r) * DD + col);
                        Ks[r][col+0]=kv.x; Ks[r][col+1]=kv.y; Ks[r][col+2]=kv.z; Ks[r][col+3]=kv.w;
                    }
                }
                __syncthreads();
                float sacc[2][4];
#pragma unroll
                for (int i = 0; i < 2; i++)
#pragma unroll
                    for (int j = 0; j < 4; j++) sacc[i][j] = 0.f;
#pragma unroll 8
                for (int kk = 0; kk < 64; kk++) {
                    float qv0 = Qs[2*ty+0][kk];
                    float qv1 = Qs[2*ty+1][kk];
#pragma unroll
                    for (int j = 0; j < 4; j++) {
                        float kv = Ks[4*tx+j][kk];
                        sacc[0][j] += qv0*kv;
                        sacc[1][j] += qv1*kv;
                    }
                }
#pragma unroll
                for (int i = 0; i < 2; i++) {
#pragma unroll
                    for (int j = 0; j < 4; j++) {
                        float sv = sacc[i][j] * sc;
                        if (kt*64 + 4*tx + j >= eff) sv = -1.0e30f;
                        Ss[2*ty+i][4*tx+j] = sv;
                    }
                }
                __syncthreads();
                {
                    int row = t >> 3, sub = t & 7;
                    float mo = m_s[row];
                    float mx = mo;
#pragma unroll
                    for (int c = sub; c < 64; c += 8) mx = fmaxf(mx, Ss[row][c]);
                    mx = fmaxf(mx, __shfl_xor_sync(0xffffffffu, mx, 1));
                    mx = fmaxf(mx, __shfl_xor_sync(0xffffffffu, mx, 2));
                    mx = fmaxf(mx, __shfl_xor_sync(0xffffffffu, mx, 4));
                    float sum = 0.f;
#pragma unroll
                    for (int c = sub; c < 64; c += 8) {
                        float e = __expf(Ss[row][c] - mx);
                        Ss[row][c] = e; sum += e;
                    }
                    sum += __shfl_xor_sync(0xffffffffu, sum, 1);
                    sum += __shfl_xor_sync(0xffffffffu, sum, 2);
                    sum += __shfl_xor_sync(0xffffffffu, sum, 4);
                    if (sub == 0) {
                        float alpha = __expf(mo - mx);
                        m_s[row] = mx;
                        l_s[row] = l_s[row]*alpha + sum;
                        alpha_s[row] = alpha;
                    }
                }
                __syncthreads();
#pragma unroll
                for (int i = 0; i < 2; i++) {
                    float al = alpha_s[2*ty+i];
#pragma unroll
                    for (int j = 0; j < 4; j++) accO[i][j] *= al;
                }
#pragma unroll 4
                for (int c = 0; c < 64; c++) {
                    float p0 = Ss[2*ty+0][c];
                    float p1 = Ss[2*ty+1][c];
#pragma unroll
                    for (int j = 0; j < 4; j++) {
                        float vv = Ks[c][4*tx+j];
                        accO[0][j] += p0*vv;
                        accO[1][j] += p1*vv;
                    }
                }
                __syncthreads();
            }
        }

        // store: attention rows [0, qcnt), zeros for rows [qcnt, wlen-q0)
#pragma unroll
        for (int i = 0; i < 2; i++) {
            int rloc = 2*ty + i;
            if (q0 + rloc >= wlen) continue;
            size_t idx = base + (size_t)(st + q0 + rloc) * DD + 4*tx;
            if (rloc < qcnt) {
                float inv = 1.f / l_s[rloc];
#pragma unroll
                for (int j = 0; j < 4; j++)
                    split_store(accO[i][j] * inv, gb_lout_h, gb_lout_l, idx + j);
            } else {
                *(uint2*)(gb_lout_h + idx) = make_uint2(0u, 0u);
                *(uint2*)(gb_lout_l + idx) = make_uint2(0u, 0u);
            }
        }
        __syncthreads();
    }
}

// ---------------- launch ----------------
extern "C" void kernel_launch(void* const* d_in, const int* in_sizes, int n_in,
                              void* d_out, int out_size)
{
    const float* x     = (const float*)d_in[0];
    const float* ln_ag = (const float*)d_in[1];
    const float* ln_ab = (const float*)d_in[2];
    const float* ln_bg = (const float*)d_in[3];
    const float* ln_bb = (const float*)d_in[4];
    const float* Wq    = (const float*)d_in[5];
    const float* bq    = (const float*)d_in[6];
    const float* Wk    = (const float*)d_in[7];
    const float* Wv    = (const float*)d_in[8];
    const float* bv    = (const float*)d_in[9];
    const float* Wo    = (const float*)d_in[10];
    const float* bo    = (const float*)d_in[11];
    const float* Wp    = (const float*)d_in[12];
    const float* bp    = (const float*)d_in[13];
    const float* Wproj = (const float*)d_in[14];
    const float* bproj = (const float*)d_in[15];
    float* out = (float*)d_out;

    void *p_gout, *p_lh, *p_ll;
    void *p_gh, *p_gl, *p_qh, *p_ql, *p_kh, *p_kl, *p_vh, *p_vl;
    void *p_ah, *p_al, *p_oh, *p_ol;
    void *p_wqh, *p_wql, *p_wkh, *p_wkl, *p_wvh, *p_wvl, *p_woh, *p_wol, *p_wph, *p_wpl;
    cudaGetSymbolAddress(&p_gout, g_gout);
    cudaGetSymbolAddress(&p_lh, gb_lout_h);  cudaGetSymbolAddress(&p_ll, gb_lout_l);
    cudaGetSymbolAddress(&p_gh, gb_globe_h); cudaGetSymbolAddress(&p_gl, gb_globe_l);
    cudaGetSymbolAddress(&p_qh, gb_q_h);     cudaGetSymbolAddress(&p_ql, gb_q_l);
    cudaGetSymbolAddress(&p_kh, gb_k_h);     cudaGetSymbolAddress(&p_kl, gb_k_l);
    cudaGetSymbolAddress(&p_vh, gb_v_h);     cudaGetSymbolAddress(&p_vl, gb_v_l);
    cudaGetSymbolAddress(&p_ah, gb_attn_h);  cudaGetSymbolAddress(&p_al, gb_attn_l);
    cudaGetSymbolAddress(&p_oh, gb_gout_h);  cudaGetSymbolAddress(&p_ol, gb_gout_l);
    cudaGetSymbolAddress(&p_wqh, gb_wq_h);   cudaGetSymbolAddress(&p_wql, gb_wq_l);
    cudaGetSymbolAddress(&p_wkh, gb_wk_h);   cudaGetSymbolAddress(&p_wkl, gb_wk_l);
    cudaGetSymbolAddress(&p_wvh, gb_wv_h);   cudaGetSymbolAddress(&p_wvl, gb_wv_l);
    cudaGetSymbolAddress(&p_woh, gb_wo_h);   cudaGetSymbolAddress(&p_wol, gb_wo_l);
    cudaGetSymbolAddress(&p_wph, gb_wp_h);   cudaGetSymbolAddress(&p_wpl, gb_wp_l);

    cudaFuncSetAttribute(gemm_bf16lm, cudaFuncAttributeMaxDynamicSharedMemorySize, GEMM_SMEM_BYTES);
    cudaFuncSetAttribute(attn_global_mma, cudaFuncAttributeMaxDynamicSharedMemorySize, ATT_SMEM_BYTES);

    // 0) LayerNorms
    ln_kernel<<<MROWS, 256>>>(x, ln_ag, ln_ab, ln_bg, ln_bb);

    // 1) merged weight split (all 5 weights)
    const int NCONV = 4*W1M4 + W2M4;
    conv_split_all<<<(NCONV+255)/256, 256>>>((const float4*)Wq, (const float4*)Wk,
                                             (const float4*)Wv, (const float4*)Wo,
                                             (const float4*)Wproj);

    // 2-4) QKV projections (bf16 hi/lo outputs; V transposed)
    dim3 ggrid(DD/128, MROWS/128);
    gemm_bf16lm<<<ggrid, 256, GEMM_SMEM_BYTES>>>((__nv_bfloat16*)p_gh, (__nv_bfloat16*)p_gl,
        nullptr, nullptr,
        (__nv_bfloat16*)p_wqh, (__nv_bfloat16*)p_wql, bq, nullptr,
        (__nv_bfloat16*)p_qh, (__nv_bfloat16*)p_ql, DD, DD, DD, DD, 0, 32, 0);
    gemm_bf16lm<<<ggrid, 256, GEMM_SMEM_BYTES>>>((__nv_bfloat16*)p_gh, (__nv_bfloat16*)p_gl,
        nullptr, nullptr,
        (__nv_bfloat16*)p_wkh, (__nv_bfloat16*)p_wkl, nullptr, nullptr,
        (__nv_bfloat16*)p_kh, (__nv_bfloat16*)p_kl, DD, DD, DD, DD, 0, 32, 0);
    gemm_bf16lm<<<ggrid, 256, GEMM_SMEM_BYTES>>>((__nv_bfloat16*)p_gh, (__nv_bfloat16*)p_gl,
        nullptr, nullptr,
        (__nv_bfloat16*)p_wvh, (__nv_bfloat16*)p_wvl, bv, nullptr,
        (__nv_bfloat16*)p_vh, (__nv_bfloat16*)p_vl, DD, DD, DD, DD, 0, 32, 1);

    // 5) Global causal attention (K-tile register prefetch)
    attn_global_mma<<<dim3(16, BB*HH), 256, ATT_SMEM_BYTES>>>();

    // 6) Output projection (fp32 gout for predictor + hi/lo for Wproj)
    gemm_bf16lm<<<ggrid, 256, GEMM_SMEM_BYTES>>>((__nv_bfloat16*)p_ah, (__nv_bfloat16*)p_al,
        nullptr, nullptr,
        (__nv_bfloat16*)p_woh, (__nv_bfloat16*)p_wol, bo, (float*)p_gout,
        (__nv_bfloat16*)p_oh, (__nv_bfloat16*)p_ol, DD, DD, DD, DD, 0, 32, 0);

    // 7-9) Span predictor + params
    pred_partA<<<dim3(BB, 16), 256>>>();
    pred_partB<<<BB, 256>>>(Wp, bp);
    params_kernel<<<1, 1>>>();

    // 10) Local span attention (zero-fills rows [eff, wlen) itself)
    attn_local_kernel<<<dim3(BB*HH, 8, 16), 256>>>();

    // 11) Fused final projection: out = [local_out | globe_out] @ Wproj^T + bproj
    gemm_bf16lm<<<ggrid, 256, GEMM_SMEM_BYTES>>>((__nv_bfloat16*)p_lh, (__nv_bfloat16*)p_ll,
        (__nv_bfloat16*)p_oh, (__nv_bfloat16*)p_ol,
        (__nv_bfloat16*)p_wph, (__nv_bfloat16*)p_wpl, bproj, out,
        nullptr, nullptr, DD, DD, 2*DD, 2*DD, 0, 32, 0);
}

// round 15
// speedup vs baseline: 1.0650x; 1.0059x over previous
#include <cuda_runtime.h>
#include <cuda_bf16.h>
#include <math.h>

#define BB 4
#define SS 1024
#define DD 1024
#define HH 16
#define HD 64
#define MROWS (BB*SS)

// ---------------- scratch (device globals; no allocation) ----------------
__device__ float g_local[MROWS*DD];
__device__ float g_gout[MROWS*DD];
__device__ float g_base[BB];
__device__ float g_pp[BB*16*DD];

// bf16 hi/lo planes
__device__ __nv_bfloat16 gb_globe_h[MROWS*DD], gb_globe_l[MROWS*DD];
__device__ __nv_bfloat16 gb_q_h[MROWS*DD],    gb_q_l[MROWS*DD];
__device__ __nv_bfloat16 gb_k_h[MROWS*DD],    gb_k_l[MROWS*DD];
__device__ __nv_bfloat16 gb_v_h[MROWS*DD],    gb_v_l[MROWS*DD];   // transposed [b][h][d][s]
__device__ __nv_bfloat16 gb_attn_h[MROWS*DD], gb_attn_l[MROWS*DD];
__device__ __nv_bfloat16 gb_gout_h[MROWS*DD], gb_gout_l[MROWS*DD];
__device__ __nv_bfloat16 gb_lout_h[MROWS*DD], gb_lout_l[MROWS*DD];
__device__ __nv_bfloat16 gb_wq_h[DD*DD], gb_wq_l[DD*DD];
__device__ __nv_bfloat16 gb_wk_h[DD*DD], gb_wk_l[DD*DD];
__device__ __nv_bfloat16 gb_wv_h[DD*DD], gb_wv_l[DD*DD];
__device__ __nv_bfloat16 gb_wo_h[DD*DD], gb_wo_l[DD*DD];
__device__ __nv_bfloat16 gb_wp_h[DD*2*DD], gb_wp_l[DD*2*DD];

struct SpanParams {
    int win, span_len, local_max;
    float span_mean, temp;
};
__device__ SpanParams g_params;

// ---------------- helpers ----------------
__device__ __forceinline__ void split_pack(float x0, float x1, unsigned &hi, unsigned &lo)
{
    __nv_bfloat16 h0 = __float2bfloat16(x0);
    __nv_bfloat16 h1 = __float2bfloat16(x1);
    float f0 = __bfloat162float(h0), f1 = __bfloat162float(h1);
    __nv_bfloat16 l0 = __float2bfloat16(x0 - f0);
    __nv_bfloat16 l1 = __float2bfloat16(x1 - f1);
    hi = ((unsigned)__bfloat16_as_ushort(h1) << 16) | (unsigned)__bfloat16_as_ushort(h0);
    lo = ((unsigned)__bfloat16_as_ushort(l1) << 16) | (unsigned)__bfloat16_as_ushort(l0);
}

__device__ __forceinline__ void split_store(float v, __nv_bfloat16* hi, __nv_bfloat16* lo, size_t idx)
{
    __nv_bfloat16 h = __float2bfloat16(v);
    hi[idx] = h;
    lo[idx] = __float2bfloat16(v - __bfloat162float(h));
}

__device__ __forceinline__ void mma_bf16(float c[4],
                                         unsigned a0, unsigned a1, unsigned a2, unsigned a3,
                                         unsigned b0, unsigned b1)
{
    asm volatile("mma.sync.aligned.m16n8k16.row.col.f32.bf16.bf16.f32 "
                 "{%0,%1,%2,%3}, {%4,%5,%6,%7}, {%8,%9}, {%0,%1,%2,%3};"
                 : "+f"(c[0]), "+f"(c[1]), "+f"(c[2]), "+f"(c[3])
                 : "r"(a0), "r"(a1), "r"(a2), "r"(a3), "r"(b0), "r"(b1));
}

__device__ __forceinline__ void ldsm4(unsigned &r0, unsigned &r1, unsigned &r2, unsigned &r3, unsigned addr)
{
    asm volatile("ldmatrix.sync.aligned.m8n8.x4.shared.b16 {%0,%1,%2,%3}, [%4];"
                 : "=r"(r0), "=r"(r1), "=r"(r2), "=r"(r3) : "r"(addr));
}

__device__ __forceinline__ void cpa16(unsigned saddr, const void* g)
{
    asm volatile("cp.async.ca.shared.global [%0], [%1], 16;" :: "r"(saddr), "l"(g));
}

// ---------------- merged weight split (all 5 weights, 1 launch) ----------
#define W1M4 (DD*DD/4)
#define W2M4 (DD*2*DD/4)
__global__ void conv_split_all(const float4* __restrict__ wq, const float4* __restrict__ wk,
                               const float4* __restrict__ wv, const float4* __restrict__ wo,
                               const float4* __restrict__ wp)
{
    int i = blockIdx.x * blockDim.x + threadIdx.x;
    const float4* src;
    __nv_bfloat16 *hi, *lo;
    int off;
    if (i < W1M4)            { src = wq; hi = gb_wq_h; lo = gb_wq_l; off = i; }
    else if (i < 2*W1M4)     { src = wk; hi = gb_wk_h; lo = gb_wk_l; off = i - W1M4; }
    else if (i < 3*W1M4)     { src = wv; hi = gb_wv_h; lo = gb_wv_l; off = i - 2*W1M4; }
    else if (i < 4*W1M4)     { src = wo; hi = gb_wo_h; lo = gb_wo_l; off = i - 3*W1M4; }
    else if (i < 4*W1M4+W2M4){ src = wp; hi = gb_wp_h; lo = gb_wp_l; off = i - 4*W1M4; }
    else return;
    float4 v = src[off];
    unsigned h0, l0, h1, l1;
    split_pack(v.x, v.y, h0, l0);
    split_pack(v.z, v.w, h1, l1);
    *(uint2*)(hi + (size_t)off*4) = make_uint2(h0, h1);
    *(uint2*)(lo + (size_t)off*4) = make_uint2(l0, l1);
}

// ---------------- LayerNorm: fp32 local + bf16 hi/lo globe ----------------
__global__ void ln_kernel(const float* __restrict__ x,
                          const float* __restrict__ ga, const float* __restrict__ ba,
                          const float* __restrict__ gb, const float* __restrict__ bb)
{
    __shared__ float red[256];
    int row = blockIdx.x;
    int t = threadIdx.x;
    const float* xr = x + (size_t)row * DD;
    float v[4];
    float s = 0.f;
#pragma unroll
    for (int k = 0; k < 4; k++) { v[k] = xr[t + 256*k]; s += v[k]; }
    red[t] = s; __syncthreads();
    for (int o = 128; o > 0; o >>= 1) { if (t < o) red[t] += red[t+o]; __syncthreads(); }
    float mean = red[0] * (1.0f/DD);
    __syncthreads();
    float s2 = 0.f;
#pragma unroll
    for (int k = 0; k < 4; k++) { float d0 = v[k]-mean; s2 += d0*d0; }
    red[t] = s2; __syncthreads();
    for (int o = 128; o > 0; o >>= 1) { if (t < o) red[t] += red[t+o]; __syncthreads(); }
    float rs = rsqrtf(red[0]*(1.0f/DD) + 1e-5f);
#pragma unroll
    for (int k = 0; k < 4; k++) {
        int c = t + 256*k;
        float nh = (v[k]-mean)*rs;
        size_t idx = (size_t)row*DD + c;
        g_local[idx] = nh*ga[c] + ba[c];
        split_store(nh*gb[c] + bb[c], gb_globe_h, gb_globe_l, idx);
    }
}

// ---------------- bf16x3 GEMM: cp.async + ldmatrix, double-buffered -------
// (R12-measured best configuration: 80B rows, 2-stage, .ca, dual-A fusion)
#define GSM_ROWB 80
#define GSM_PLANE 10240
#define GSM_BUF 40960
#define GEMM_SMEM_BYTES (2*GSM_BUF)

__global__ void __launch_bounds__(256, 2) gemm_bf16lm(
    const __nv_bfloat16* __restrict__ Ah, const __nv_bfloat16* __restrict__ Al,
    const __nv_bfloat16* __restrict__ A2h, const __nv_bfloat16* __restrict__ A2l,
    const __nv_bfloat16* __restrict__ Wh, const __nv_bfloat16* __restrict__ Wl,
    const float* __restrict__ bias, float* __restrict__ C,
    __nv_bfloat16* __restrict__ Chi, __nv_bfloat16* __restrict__ Clo,
    int N, int lda, int K, int ldw, int koff, int k1ch, int transv)
{
    extern __shared__ char sm8[];
    unsigned sbase = (unsigned)__cvta_generic_to_shared(sm8);

    int t = threadIdx.x;
    int wid = t >> 5, lane = t & 31;
    int warp_m = wid >> 2, warp_n = wid & 3;
    int bm = blockIdx.y * 128, bn = blockIdx.x * 128;
    int qq = lane >> 2, rr = lane & 3;

    int crow = t >> 1;
    int csp = t & 1;
    const __nv_bfloat16* gAh = Ah + (size_t)(bm + crow) * lda + csp*16;
    const __nv_bfloat16* gAl = Al + (size_t)(bm + crow) * lda + csp*16;
    const __nv_bfloat16* gA2h = A2h ? A2h + (size_t)(bm + crow) * lda + csp*16 : gAh;
    const __nv_bfloat16* gA2l = A2l ? A2l + (size_t)(bm + crow) * lda + csp*16 : gAl;
    const __nv_bfloat16* gWh = Wh + (size_t)(bn + crow) * ldw + koff + csp*16;
    const __nv_bfloat16* gWl = Wl + (size_t)(bn + crow) * ldw + koff + csp*16;
    unsigned dOff = crow*GSM_ROWB + csp*32;

    int mq = lane >> 3, j = lane & 7;
    unsigned aoff = (warp_m*64 + (mq&1)*8 + j)*GSM_ROWB + (mq>>1)*16;
    unsigned boff = (warp_n*32 + (mq>>1)*8 + j)*GSM_ROWB + (mq&1)*16;

    float acc[4][4][4];
#pragma unroll
    for (int im = 0; im < 4; im++)
#pragma unroll
        for (int in = 0; in < 4; in++)
#pragma unroll
            for (int r = 0; r < 4; r++) acc[im][in][r] = 0.f;

#define ISSUE(buf, kc) do { \
    unsigned d = sbase + (buf)*GSM_BUF + dOff; \
    const __nv_bfloat16* sh_ = ((kc) < k1ch) ? gAh + (size_t)(kc)*32 : gA2h + (size_t)((kc) - k1ch)*32; \
    const __nv_bfloat16* sl_ = ((kc) < k1ch) ? gAl + (size_t)(kc)*32 : gA2l + (size_t)((kc) - k1ch)*32; \
    cpa16(d,                   sh_); \
    cpa16(d+16,                sh_ + 8); \
    cpa16(d+GSM_PLANE,         sl_); \
    cpa16(d+GSM_PLANE+16,      sl_ + 8); \
    cpa16(d+2*GSM_PLANE,       gWh + (size_t)(kc)*32); \
    cpa16(d+2*GSM_PLANE+16,    gWh + (size_t)(kc)*32 + 8); \
    cpa16(d+3*GSM_PLANE,       gWl + (size_t)(kc)*32); \
    cpa16(d+3*GSM_PLANE+16,    gWl + (size_t)(kc)*32 + 8); \
    asm volatile("cp.async.commit_group;"); \
} while (0)

    int nch = K / 32;
    ISSUE(0, 0);
    if (nch > 1) ISSUE(1, 1);

    for (int c = 0; c < nch; c++) {
        int cur = c & 1;
        if (c + 1 < nch) asm volatile("cp.async.wait_group 1;");
        else             asm volatile("cp.async.wait_group 0;");
        __syncthreads();

        unsigned pah = sbase + cur*GSM_BUF + aoff;
        unsigned pal = pah + GSM_PLANE;
        unsigned pbh = sbase + cur*GSM_BUF + 2*GSM_PLANE + boff;
        unsigned pbl = pbh + GSM_PLANE;
#pragma unroll
        for (int ks = 0; ks < 2; ks++) {
            unsigned kb = ks*32;
            unsigned bh0[4], bh1[4], bl0[4], bl1[4];
            {
                unsigned r0,r1,r2,r3;
                ldsm4(r0,r1,r2,r3, pbh + kb);
                bh0[0]=r0; bh1[0]=r1; bh0[1]=r2; bh1[1]=r3;
                ldsm4(r0,r1,r2,r3, pbh + 1280 + kb);
                bh0[2]=r0; bh1[2]=r1; bh0[3]=r2; bh1[3]=r3;
                ldsm4(r0,r1,r2,r3, pbl + kb);
                bl0[0]=r0; bl1[0]=r1; bl0[1]=r2; bl1[1]=r3;
                ldsm4(r0,r1,r2,r3, pbl + 1280 + kb);
                bl0[2]=r0; bl1[2]=r1; bl0[3]=r2; bl1[3]=r3;
            }
#pragma unroll
            for (int im = 0; im < 4; im++) {
                unsigned ah0,ah1,ah2,ah3, al0,al1,al2,al3;
                ldsm4(ah0,ah1,ah2,ah3, pah + im*1280 + kb);
                ldsm4(al0,al1,al2,al3, pal + im*1280 + kb);
#pragma unroll
                for (int in = 0; in < 4; in++) {
                    mma_bf16(acc[im][in], ah0,ah1,ah2,ah3, bh0[in], bh1[in]);
                    mma_bf16(acc[im][in], ah0,ah1,ah2,ah3, bl0[in], bl1[in]);
                    mma_bf16(acc[im][in], al0,al1,al2,al3, bh0[in], bh1[in]);
                }
            }
        }
        __syncthreads();
        if (c + 2 < nch) ISSUE(cur, c + 2);
    }
#undef ISSUE

    // epilogue
#pragma unroll
    for (int im = 0; im < 4; im++) {
        int r0 = bm + warp_m*64 + im*16 + qq;
#pragma unroll
        for (int in = 0; in < 4; in++) {
            int c0 = bn + warp_n*32 + in*8 + 2*rr;
            float b0v = bias ? bias[c0]   : 0.f;
            float b1v = bias ? bias[c0+1] : 0.f;
#pragma unroll
            for (int half = 0; half < 2; half++) {
                int m = r0 + half*8;
                float v0 = acc[im][in][2*half + 0] + b0v;
                float v1 = acc[im][in][2*half + 1] + b1v;
                if (transv) {
                    size_t i0 = ((size_t)((m>>10)*HH + (c0>>6))*HD + (c0&63))*SS + (m&1023);
                    size_t i1 = ((size_t)((m>>10)*HH + ((c0+1)>>6))*HD + ((c0+1)&63))*SS + (m&1023);
                    split_store(v0, Chi, Clo, i0);
                    split_store(v1, Chi, Clo, i1);
                } else {
                    size_t idx = (size_t)m * N + c0;
                    if (C) { C[idx] = v0; C[idx+1] = v1; }
                    if (Chi) {
                        split_store(v0, Chi, Clo, idx);
                        split_store(v1, Chi, Clo, idx+1);
                    }
                }
            }
        }
    }
}

// ---------------- Global causal attention: 2 barriers/iter, V planes ------
#define AW 36
#define A_QH 0
#define A_QL 2304
#define A_KH 4608
#define A_KL 6912
#define A_VH 9216
#define A_VL 11520
#define A_PH 13824
#define A_PL 16128
#define A_ST 18432               // float [64][66] = 4224
#define A_MS (18432 + 4224)
#define ATT_SMEM_WORDS (18432 + 4224 + 192)
#define ATT_SMEM_BYTES (ATT_SMEM_WORDS*4)

__global__ void __launch_bounds__(256, 2) attn_global_mma()
{
    extern __shared__ unsigned usm[];
    float* STm = (float*)(usm + A_ST);
    float* m_s = (float*)(usm + A_MS);
    float* l_s = m_s + 64;
    float* al_s = l_s + 64;

    int qt = 15 - (int)blockIdx.x;
    int bh = blockIdx.y;
    int b = bh >> 4, h = bh & 15;
    int t = threadIdx.x;
    int lane = t & 31, wid = t >> 5;
    int tx = t & 15, ty = t >> 4;
    int warp_m = wid & 3, warp_n = wid >> 2;
    int qq = lane >> 2, rr = lane & 3;
    int q0 = qt * 64;
    size_t baseQ = (size_t)b * SS * DD + h * HD;
    size_t baseVT = ((size_t)(b*HH + h)) * HD * SS;

    // load Q tile hi/lo
#pragma unroll
    for (int i = 0; i < 4; i++) {
        int r = ty + 16*i;
        size_t gi = baseQ + (size_t)(q0 + r) * DD + 4*tx;
        uint2 vh = *(const uint2*)(gb_q_h + gi);
        uint2 vl = *(const uint2*)(gb_q_l + gi);
        usm[A_QH + r*AW + 2*tx] = vh.x;  usm[A_QH + r*AW + 2*tx + 1] = vh.y;
        usm[A_QL + r*AW + 2*tx] = vl.x;  usm[A_QL + r*AW + 2*tx + 1] = vl.y;
    }
    if (t < 64) { m_s[t] = -3.0e38f; l_s[t] = 0.f; }

    float oacc[4][4];
#pragma unroll
    for (int nn = 0; nn < 4; nn++)
#pragma unroll
        for (int r = 0; r < 4; r++) oacc[nn][r] = 0.f;

    // prefetch + store K(0) to smem
    uint2 kvh[4], kvl[4];
#pragma unroll
    for (int i = 0; i < 4; i++) {
        int r = ty + 16*i;
        size_t gi = baseQ + (size_t)r * DD + 4*tx;
        kvh[i] = *(const uint2*)(gb_k_h + gi);
        kvl[i] = *(const uint2*)(gb_k_l + gi);
    }
#pragma unroll
    for (int i = 0; i < 4; i++) {
        int r = ty + 16*i;
        usm[A_KH + r*AW + 2*tx] = kvh[i].x;  usm[A_KH + r*AW + 2*tx + 1] = kvh[i].y;
        usm[A_KL + r*AW + 2*tx] = kvl[i].x;  usm[A_KL + r*AW + 2*tx + 1] = kvl[i].y;
    }
    __syncthreads();

    for (int kt = 0; kt <= qt; kt++) {
        int k0 = kt * 64;
        // ---- phase 1: S^T = K @ Q^T -> STm; issue V(kt) + K(kt+1) loads ----
        {
            float c4[4][4];
#pragma unroll
            for (int nn = 0; nn < 4; nn++)
#pragma unroll
                for (int r = 0; r < 4; r++) c4[nn][r] = 0.f;
#pragma unroll
            for (int ks = 0; ks < 4; ks++) {
                int kw = ks*8;
                int ar = warp_m*16 + qq;
                unsigned ah0 = usm[A_KH +  ar   *AW + kw+rr];
                unsigned ah1 = usm[A_KH + (ar+8)*AW + kw+rr];
                unsigned ah2 = usm[A_KH +  ar   *AW + kw+4+rr];
                unsigned ah3 = usm[A_KH + (ar+8)*AW + kw+4+rr];
                unsigned al0 = usm[A_KL +  ar   *AW + kw+rr];
                unsigned al1 = usm[A_KL + (ar+8)*AW + kw+rr];
                unsigned al2 = usm[A_KL +  ar   *AW + kw+4+rr];
                unsigned al3 = usm[A_KL + (ar+8)*AW + kw+4+rr];
#pragma unroll
                for (int nn = 0; nn < 4; nn++) {
                    int br = warp_n*32 + nn*8 + qq;
                    unsigned bh0 = usm[A_QH + br*AW + kw+rr];
                    unsigned bh1 = usm[A_QH + br*AW + kw+4+rr];
                    unsigned bl0 = usm[A_QL + br*AW + kw+rr];
                    unsigned bl1 = usm[A_QL + br*AW + kw+4+rr];
                    mma_bf16(c4[nn], ah0, ah1, ah2, ah3, bh0, bh1);
                    mma_bf16(c4[nn], ah0, ah1, ah2, ah3, bl0, bl1);
                    mma_bf16(c4[nn], al0, al1, al2, al3, bh0, bh1);
                }
            }
            int krow = warp_m*16 + qq;
#pragma unroll
            for (int nn = 0; nn < 4; nn++) {
                int qc = warp_n*32 + nn*8 + 2*rr;
                STm[ krow   *66 + qc    ] = c4[nn][0];
                STm[ krow   *66 + qc + 1] = c4[nn][1];
                STm[(krow+8)*66 + qc    ] = c4[nn][2];
                STm[(krow+8)*66 + qc + 1] = c4[nn][3];
            }
        }
        uint2 vvh[4], vvl[4];
#pragma unroll
        for (int i = 0; i < 4; i++) {
            int d = ty + 16*i;
            size_t gi = baseVT + (size_t)d * SS + k0 + 4*tx;
            vvh[i] = *(const uint2*)(gb_v_h + gi);
            vvl[i] = *(const uint2*)(gb_v_l + gi);
        }
        if (kt < qt) {
#pragma unroll
            for (int i = 0; i < 4; i++) {
                int r = ty + 16*i;
                size_t gi = baseQ + (size_t)(k0 + 64 + r) * DD + 4*tx;
                kvh[i] = *(const uint2*)(gb_k_h + gi);
                kvl[i] = *(const uint2*)(gb_k_l + gi);
            }
        }
        __syncthreads();   // sync a

        // ---- phase 2: softmax (STm->P); store V -> VH/VL; store K(kt+1) ----
        {
            int row = t >> 2, sub = t & 3;
            int qglob = q0 + row;
            float mo = m_s[row];
            float mx = mo;
            float ev[16];
#pragma unroll
            for (int j2 = 0; j2 < 16; j2++) {
                int key = sub*16 + j2;
                float sv = STm[key*66 + row] * 0.125f;
                if (k0 + key > qglob) sv = -1.0e30f;
                ev[j2] = sv;
                mx = fmaxf(mx, sv);
            }
            mx = fmaxf(mx, __shfl_xor_sync(0xffffffffu, mx, 1));
            mx = fmaxf(mx, __shfl_xor_sync(0xffffffffu, mx, 2));
            float sum = 0.f;
#pragma unroll
            for (int j2 = 0; j2 < 16; j2++) {
                float e = __expf(ev[j2] - mx);
                ev[j2] = e; sum += e;
            }
#pragma unroll
            for (int j2 = 0; j2 < 8; j2++) {
                unsigned hi, lo;
                split_pack(ev[2*j2], ev[2*j2+1], hi, lo);
                usm[A_PH + row*AW + sub*8 + j2] = hi;
                usm[A_PL + row*AW + sub*8 + j2] = lo;
            }
            sum += __shfl_xor_sync(0xffffffffu, sum, 1);
            sum += __shfl_xor_sync(0xffffffffu, sum, 2);
            if (sub == 0) {
                float alpha = __expf(mo - mx);
                m_s[row] = mx;
                l_s[row] = l_s[row] * alpha + sum;
                al_s[row] = alpha;
            }
        }
#pragma unroll
        for (int i = 0; i < 4; i++) {
            int d = ty + 16*i;
            usm[A_VH + d*AW + 2*tx] = vvh[i].x;  usm[A_VH + d*AW + 2*tx + 1] = vvh[i].y;
            usm[A_VL + d*AW + 2*tx] = vvl[i].x;  usm[A_VL + d*AW + 2*tx + 1] = vvl[i].y;
        }
        if (kt < qt) {
#pragma unroll
            for (int i = 0; i < 4; i++) {
                int r = ty + 16*i;
                usm[A_KH + r*AW + 2*tx] = kvh[i].x;  usm[A_KH + r*AW + 2*tx + 1] = kvh[i].y;
                usm[A_KL + r*AW + 2*tx] = kvl[i].x;  usm[A_KL + r*AW + 2*tx + 1] = kvl[i].y;
            }
        }
        __syncthreads();   // sync b

        // ---- phase 3: O *= alpha ; O += P @ V ----
        {
            int qr = warp_m*16 + qq;
            float a0 = al_s[qr], a1 = al_s[qr + 8];
#pragma unroll
            for (int nn = 0; nn < 4; nn++) {
                oacc[nn][0] *= a0; oacc[nn][1] *= a0;
                oacc[nn][2] *= a1; oacc[nn][3] *= a1;
            }
#pragma unroll
            for (int ks = 0; ks < 4; ks++) {
                int kw = ks*8;
                int ar = warp_m*16 + qq;
                unsigned ah0 = usm[A_PH +  ar   *AW + kw+rr];
                unsigned ah1 = usm[A_PH + (ar+8)*AW + kw+rr];
                unsigned ah2 = usm[A_PH +  ar   *AW + kw+4+rr];
                unsigned ah3 = usm[A_PH + (ar+8)*AW + kw+4+rr];
                unsigned al0 = usm[A_PL +  ar   *AW + kw+rr];
                unsigned al1 = usm[A_PL + (ar+8)*AW + kw+rr];
                unsigned al2 = usm[A_PL +  ar   *AW + kw+4+rr];
                unsigned al3 = usm[A_PL + (ar+8)*AW + kw+4+rr];
#pragma unroll
                for (int nn = 0; nn < 4; nn++) {
                    int br = warp_n*32 + nn*8 + qq;
                    unsigned bh0 = usm[A_VH + br*AW + kw+rr];
                    unsigned bh1 = usm[A_VH + br*AW + kw+4+rr];
                    unsigned bl0 = usm[A_VL + br*AW + kw+rr];
                    unsigned bl1 = usm[A_VL + br*AW + kw+4+rr];
                    mma_bf16(oacc[nn], ah0, ah1, ah2, ah3, bh0, bh1);
                    mma_bf16(oacc[nn], ah0, ah1, ah2, ah3, bl0, bl1);
                    mma_bf16(oacc[nn], al0, al1, al2, al3, bh0, bh1);
                }
            }
        }
        // no end-of-loop barrier: next phase-1 writes (STm) were last read in
        // phase 2 (separated by sync b); next phase-2 writes (KH/VH/PH) are
        // separated from this phase-3's reads by the next sync a.
    }

    // write O hi/lo (normalized)
    {
        int qr = warp_m*16 + qq;
        float inv0 = 1.f / l_s[qr];
        float inv1 = 1.f / l_s[qr + 8];
#pragma unroll
        for (int nn = 0; nn < 4; nn++) {
            int dc = warp_n*32 + nn*8 + 2*rr;
            size_t i0 = baseQ + (size_t)(q0 + qr) * DD + dc;
            size_t i1 = baseQ + (size_t)(q0 + qr + 8) * DD + dc;
            split_store(oacc[nn][0] * inv0, gb_attn_h, gb_attn_l, i0);
            split_store(oacc[nn][1] * inv0, gb_attn_h, gb_attn_l, i0+1);
            split_store(oacc[nn][2] * inv1, gb_attn_h, gb_attn_l, i1);
            split_store(oacc[nn][3] * inv1, gb_attn_h, gb_attn_l, i1+1);
        }
    }
}

// ---------------- Predictor (two-stage, parallel, deterministic) ----------
__global__ void pred_partA()
{
    int b = blockIdx.x, ch = blockIdx.y;
    int t = threadIdx.x;
#pragma unroll
    for (int c = 0; c < 4; c++) {
        int col = t + 256*c;
        float s = 0.f;
        const float* p = g_gout + ((size_t)b*SS + ch*64) * DD + col;
        for (int r = 0; r < 64; r++) s += p[(size_t)r * DD];
        g_pp[((size_t)b*16 + ch)*DD + col] = s;
    }
}

__global__ void pred_partB(const float* __restrict__ Wp, const float* __restrict__ bp)
{
    __shared__ float red[256];
    int b = blockIdx.x;
    int t = threadIdx.x;
    float part = 0.f;
#pragma unroll
    for (int c = 0; c < 4; c++) {
        int col = t + 256*c;
        float s = 0.f;
#pragma unroll
        for (int ch = 0; ch < 16; ch++)
            s += g_pp[((size_t)b*16 + ch)*DD + col];
        part += (s * (1.0f/SS)) * Wp[col];
    }
    red[t] = part; __syncthreads();
    for (int o = 128; o > 0; o >>= 1) { if (t < o) red[t] += red[t+o]; __syncthreads(); }
    if (t == 0) {
        float z = red[0] + bp[0];
        g_base[b] = 1.f / (1.f + expf(-z));
    }
}

// ---------------- Span params ----------------
__global__ void params_kernel()
{
    float smf = (g_base[0] + g_base[1] + g_base[2] + g_base[3]) * 0.25f;
    double sm = (double)smf;
    int win = (int)(256.0 * sm);      if (win < 1) win = 1;
    int span_len = (int)(512.0 * sm); if (span_len < 1) span_len = 1;
    int lm = 512;
    if (span_len < lm) lm = span_len;
    if (win < lm) lm = win;
    g_params.win = win;
    g_params.span_len = span_len;
    g_params.local_max = lm;
    g_params.span_mean = smf;
    g_params.temp = (float)(1.0 + 0.01 * (1.0 - sm));
}

// ---------------- Local span attention (K == V); zero-fills [eff, wlen) ---
__global__ void __launch_bounds__(256) attn_local_kernel()
{
    __shared__ float Qs[32][65];
    __shared__ float Ks[64][65];
    __shared__ float Ss[32][65];
    __shared__ float m_s[32], l_s[32], alpha_s[32];

    SpanParams p = g_params;
    int bh = blockIdx.x;  int b = bh >> 4, h = bh & 15;
    int qt = blockIdx.y;
    int t = threadIdx.x;
    int tx = t & 15, ty = t >> 4;
    size_t base = (size_t)b * SS * DD + h * HD;
    float sc = 0.35355339059327373f / p.temp;

    for (int w = blockIdx.z; w * p.win < SS; w += (int)gridDim.z) {
        int st = w * p.win;
        int en = st + p.win; if (en > SS) en = SS;
        int wlen = en - st;
        int ks0 = st - p.span_len + p.win; if (ks0 < 0) ks0 = 0;
        int ke = st + p.span_len; if (ke > SS) ke = SS;
        int klen = ke - ks0;
        int eff = (int)((double)wlen * (double)p.span_mean);
        if (eff > wlen) eff = wlen;
        if (eff > klen) eff = klen;
        if (eff > p.local_max) eff = p.local_max;
        int q0 = qt * 32;
        if (q0 >= wlen) continue;
        bool docompute = (eff > 0 && q0 < eff);
        int qcnt = 0;
        if (docompute) { qcnt = eff - q0; if (qcnt > 32) qcnt = 32; }

        float accO[2][4];
#pragma unroll
        for (int i = 0; i < 2; i++)
#pragma unroll
            for (int j = 0; j < 4; j++) accO[i][j] = 0.f;

        if (docompute) {
            {
                int col = tx * 4;
#pragma unroll
                for (int rr2 = 0; rr2 < 2; rr2++) {
                    int r = ty + rr2*16;
                    float4 qv = make_float4(0.f,0.f,0.f,0.f);
                    if (r < qcnt)
                        qv = *(const float4*)(g_local + base + (size_t)(st + q0 + r) * DD + col);
                    Qs[r][col+0]=qv.x; Qs[r][col+1]=qv.y; Qs[r][col+2]=qv.z; Qs[r][col+3]=qv.w;
                }
            }
            if (t < 32) { m_s[t] = -3.0e38f; l_s[t] = 0.f; }
            __syncthreads();

            int nkt = (eff + 63) >> 6;
            for (int kt = 0; kt < nkt; kt++) {
                {
                    int col = tx * 4;
#pragma unroll
                    for (int rr2 = 0; rr2 < 4; rr2++) {
                        int r = ty + rr2*16;
                        float4 kv = make_float4(0.f,0.f,0.f,0.f);
                        if (kt*64 + r < eff)
                            kv = *(const float4*)(g_local + base + (size_t)(ks0 + kt*64 + r) * DD + col);
                        Ks[r][col+0]=kv.x; Ks[r][col+1]=kv.y; Ks[r][col+2]=kv.z; Ks[r][col+3]=kv.w;
                    }
                }
                __syncthreads();
                float sacc[2][4];
#pragma unroll
                for (int i = 0; i < 2; i++)
#pragma unroll
                    for (int j = 0; j < 4; j++) sacc[i][j] = 0.f;
#pragma unroll 8
                for (int kk = 0; kk < 64; kk++) {
                    float qv0 = Qs[2*ty+0][kk];
                    float qv1 = Qs[2*ty+1][kk];
#pragma unroll
                    for (int j = 0; j < 4; j++) {
                        float kv = Ks[4*tx+j][kk];
                        sacc[0][j] += qv0*kv;
                        sacc[1][j] += qv1*kv;
                    }
                }
#pragma unroll
                for (int i = 0; i < 2; i++) {
#pragma unroll
                    for (int j = 0; j < 4; j++) {
                        float sv = sacc[i][j] * sc;
                        if (kt*64 + 4*tx + j >= eff) sv = -1.0e30f;
                        Ss[2*ty+i][4*tx+j] = sv;
                    }
                }
                __syncthreads();
                {
                    int row = t >> 3, sub = t & 7;
                    float mo = m_s[row];
                    float mx = mo;
#pragma unroll
                    for (int c = sub; c < 64; c += 8) mx = fmaxf(mx, Ss[row][c]);
                    mx = fmaxf(mx, __shfl_xor_sync(0xffffffffu, mx, 1));
                    mx = fmaxf(mx, __shfl_xor_sync(0xffffffffu, mx, 2));
                    mx = fmaxf(mx, __shfl_xor_sync(0xffffffffu, mx, 4));
                    float sum = 0.f;
#pragma unroll
                    for (int c = sub; c < 64; c += 8) {
                        float e = __expf(Ss[row][c] - mx);
                        Ss[row][c] = e; sum += e;
                    }
                    sum += __shfl_xor_sync(0xffffffffu, sum, 1);
                    sum += __shfl_xor_sync(0xffffffffu, sum, 2);
                    sum += __shfl_xor_sync(0xffffffffu, sum, 4);
                    if (sub == 0) {
                        float alpha = __expf(mo - mx);
                        m_s[row] = mx;
                        l_s[row] = l_s[row]*alpha + sum;
                        alpha_s[row] = alpha;
                    }
                }
                __syncthreads();
#pragma unroll
                for (int i = 0; i < 2; i++) {
                    float al = alpha_s[2*ty+i];
#pragma unroll
                    for (int j = 0; j < 4; j++) accO[i][j] *= al;
                }
#pragma unroll 4
                for (int c = 0; c < 64; c++) {
                    float p0 = Ss[2*ty+0][c];
                    float p1 = Ss[2*ty+1][c];
#pragma unroll
                    for (int j = 0; j < 4; j++) {
                        float vv = Ks[c][4*tx+j];
                        accO[0][j] += p0*vv;
                        accO[1][j] += p1*vv;
                    }
                }
                __syncthreads();
            }
        }

        // store: attention rows [0, qcnt), zeros for rows [qcnt, wlen-q0)
#pragma unroll
        for (int i = 0; i < 2; i++) {
            int rloc = 2*ty + i;
            if (q0 + rloc >= wlen) continue;
            size_t idx = base + (size_t)(st + q0 + rloc) * DD + 4*tx;
            if (rloc < qcnt) {
                float inv = 1.f / l_s[rloc];
#pragma unroll
                for (int j = 0; j < 4; j++)
                    split_store(accO[i][j] * inv, gb_lout_h, gb_lout_l, idx + j);
            } else {
                *(uint2*)(gb_lout_h + idx) = make_uint2(0u, 0u);
                *(uint2*)(gb_lout_l + idx) = make_uint2(0u, 0u);
            }
        }
        __syncthreads();
    }
}

// ---------------- launch ----------------
extern "C" void kernel_launch(void* const* d_in, const int* in_sizes, int n_in,
                              void* d_out, int out_size)
{
    const float* x     = (const float*)d_in[0];
    const float* ln_ag = (const float*)d_in[1];
    const float* ln_ab = (const float*)d_in[2];
    const float* ln_bg = (const float*)d_in[3];
    const float* ln_bb = (const float*)d_in[4];
    const float* Wq    = (const float*)d_in[5];
    const float* bq    = (const float*)d_in[6];
    const float* Wk    = (const float*)d_in[7];
    const float* Wv    = (const float*)d_in[8];
    const float* bv    = (const float*)d_in[9];
    const float* Wo    = (const float*)d_in[10];
    const float* bo    = (const float*)d_in[11];
    const float* Wp    = (const float*)d_in[12];
    const float* bp    = (const float*)d_in[13];
    const float* Wproj = (const float*)d_in[14];
    const float* bproj = (const float*)d_in[15];
    float* out = (float*)d_out;

    void *p_gout, *p_lh, *p_ll;
    void *p_gh, *p_gl, *p_qh, *p_ql, *p_kh, *p_kl, *p_vh, *p_vl;
    void *p_ah, *p_al, *p_oh, *p_ol;
    void *p_wqh, *p_wql, *p_wkh, *p_wkl, *p_wvh, *p_wvl, *p_woh, *p_wol, *p_wph, *p_wpl;
    cudaGetSymbolAddress(&p_gout, g_gout);
    cudaGetSymbolAddress(&p_lh, gb_lout_h);  cudaGetSymbolAddress(&p_ll, gb_lout_l);
    cudaGetSymbolAddress(&p_gh, gb_globe_h); cudaGetSymbolAddress(&p_gl, gb_globe_l);
    cudaGetSymbolAddress(&p_qh, gb_q_h);     cudaGetSymbolAddress(&p_ql, gb_q_l);
    cudaGetSymbolAddress(&p_kh, gb_k_h);     cudaGetSymbolAddress(&p_kl, gb_k_l);
    cudaGetSymbolAddress(&p_vh, gb_v_h);     cudaGetSymbolAddress(&p_vl, gb_v_l);
    cudaGetSymbolAddress(&p_ah, gb_attn_h);  cudaGetSymbolAddress(&p_al, gb_attn_l);
    cudaGetSymbolAddress(&p_oh, gb_gout_h);  cudaGetSymbolAddress(&p_ol, gb_gout_l);
    cudaGetSymbolAddress(&p_wqh, gb_wq_h);   cudaGetSymbolAddress(&p_wql, gb_wq_l);
    cudaGetSymbolAddress(&p_wkh, gb_wk_h);   cudaGetSymbolAddress(&p_wkl, gb_wk_l);
    cudaGetSymbolAddress(&p_wvh, gb_wv_h);   cudaGetSymbolAddress(&p_wvl, gb_wv_l);
    cudaGetSymbolAddress(&p_woh, gb_wo_h);   cudaGetSymbolAddress(&p_wol, gb_wo_l);
    cudaGetSymbolAddress(&p_wph, gb_wp_h);   cudaGetSymbolAddress(&p_wpl, gb_wp_l);

    cudaFuncSetAttribute(gemm_bf16lm, cudaFuncAttributeMaxDynamicSharedMemorySize, GEMM_SMEM_BYTES);
    cudaFuncSetAttribute(attn_global_mma, cudaFuncAttributeMaxDynamicSharedMemorySize, ATT_SMEM_BYTES);

    // 0) LayerNorms
    ln_kernel<<<MROWS, 256>>>(x, ln_ag, ln_ab, ln_bg, ln_bb);

    // 1) merged weight split (all 5 weights)
    const int NCONV = 4*W1M4 + W2M4;
    conv_split_all<<<(NCONV+255)/256, 256>>>((const float4*)Wq, (const float4*)Wk,
                                             (const float4*)Wv, (const float4*)Wo,
                                             (const float4*)Wproj);

    // 2-4) QKV projections (bf16 hi/lo outputs; V transposed)
    dim3 ggrid(DD/128, MROWS/128);
    gemm_bf16lm<<<ggrid, 256, GEMM_SMEM_BYTES>>>((__nv_bfloat16*)p_gh, (__nv_bfloat16*)p_gl,
        nullptr, nullptr,
        (__nv_bfloat16*)p_wqh, (__nv_bfloat16*)p_wql, bq, nullptr,
        (__nv_bfloat16*)p_qh, (__nv_bfloat16*)p_ql, DD, DD, DD, DD, 0, 32, 0);
    gemm_bf16lm<<<ggrid, 256, GEMM_SMEM_BYTES>>>((__nv_bfloat16*)p_gh, (__nv_bfloat16*)p_gl,
        nullptr, nullptr,
        (__nv_bfloat16*)p_wkh, (__nv_bfloat16*)p_wkl, nullptr, nullptr,
        (__nv_bfloat16*)p_kh, (__nv_bfloat16*)p_kl, DD, DD, DD, DD, 0, 32, 0);
    gemm_bf16lm<<<ggrid, 256, GEMM_SMEM_BYTES>>>((__nv_bfloat16*)p_gh, (__nv_bfloat16*)p_gl,
        nullptr, nullptr,
        (__nv_bfloat16*)p_wvh, (__nv_bfloat16*)p_wvl, bv, nullptr,
        (__nv_bfloat16*)p_vh, (__nv_bfloat16*)p_vl, DD, DD, DD, DD, 0, 32, 1);

    // 5) Global causal attention (2 barriers/iter, K prefetch, V planes)
    attn_global_mma<<<dim3(16, BB*HH), 256, ATT_SMEM_BYTES>>>();

    // 6) Output projection (fp32 gout for predictor + hi/lo for Wproj)
    gemm_bf16lm<<<ggrid, 256, GEMM_SMEM_BYTES>>>((__nv_bfloat16*)p_ah, (__nv_bfloat16*)p_al,
        nullptr, nullptr,
        (__nv_bfloat16*)p_woh, (__nv_bfloat16*)p_wol, bo, (float*)p_gout,
        (__nv_bfloat16*)p_oh, (__nv_bfloat16*)p_ol, DD, DD, DD, DD, 0, 32, 0);

    // 7-9) Span predictor + params
    pred_partA<<<dim3(BB, 16), 256>>>();
    pred_partB<<<BB, 256>>>(Wp, bp);
    params_kernel<<<1, 1>>>();

    // 10) Local span attention (zero-fills rows [eff, wlen) itself)
    attn_local_kernel<<<dim3(BB*HH, 8, 16), 256>>>();

    // 11) Fused final projection: out = [local_out | globe_out] @ Wproj^T + bproj
    gemm_bf16lm<<<ggrid, 256, GEMM_SMEM_BYTES>>>((__nv_bfloat16*)p_lh, (__nv_bfloat16*)p_ll,
        (__nv_bfloat16*)p_oh, (__nv_bfloat16*)p_ol,
        (__nv_bfloat16*)p_wph, (__nv_bfloat16*)p_wpl, bproj, out,
        nullptr, nullptr, DD, DD, 2*DD, 2*DD, 0, 32, 0);
}

// round 16
// speedup vs baseline: 1.0700x; 1.0047x over previous
#include <cuda_runtime.h>
#include <cuda_bf16.h>
#include <math.h>

#define BB 4
#define SS 1024
#define DD 1024
#define HH 16
#define HD 64
#define MROWS (BB*SS)

// ---------------- scratch (device globals; no allocation) ----------------
__device__ float g_local[MROWS*DD];
__device__ float g_gout[MROWS*DD];
__device__ float g_base[BB];
__device__ float g_pp[BB*16*DD];

// bf16 hi/lo planes
__device__ __nv_bfloat16 gb_globe_h[MROWS*DD], gb_globe_l[MROWS*DD];
__device__ __nv_bfloat16 gb_q_h[MROWS*DD],    gb_q_l[MROWS*DD];
__device__ __nv_bfloat16 gb_k_h[MROWS*DD],    gb_k_l[MROWS*DD];
__device__ __nv_bfloat16 gb_v_h[MROWS*DD],    gb_v_l[MROWS*DD];   // transposed [b][h][d][s]
__device__ __nv_bfloat16 gb_attn_h[MROWS*DD], gb_attn_l[MROWS*DD];
__device__ __nv_bfloat16 gb_gout_h[MROWS*DD], gb_gout_l[MROWS*DD];
__device__ __nv_bfloat16 gb_lout_h[MROWS*DD], gb_lout_l[MROWS*DD];
__device__ __nv_bfloat16 gb_wq_h[DD*DD], gb_wq_l[DD*DD];
__device__ __nv_bfloat16 gb_wk_h[DD*DD], gb_wk_l[DD*DD];
__device__ __nv_bfloat16 gb_wv_h[DD*DD], gb_wv_l[DD*DD];
__device__ __nv_bfloat16 gb_wo_h[DD*DD], gb_wo_l[DD*DD];
__device__ __nv_bfloat16 gb_wp_h[DD*2*DD], gb_wp_l[DD*2*DD];

struct SpanParams {
    int win, span_len, local_max;
    float span_mean, temp;
};
__device__ SpanParams g_params;

// ---------------- helpers ----------------
__device__ __forceinline__ void split_pack(float x0, float x1, unsigned &hi, unsigned &lo)
{
    __nv_bfloat16 h0 = __float2bfloat16(x0);
    __nv_bfloat16 h1 = __float2bfloat16(x1);
    float f0 = __bfloat162float(h0), f1 = __bfloat162float(h1);
    __nv_bfloat16 l0 = __float2bfloat16(x0 - f0);
    __nv_bfloat16 l1 = __float2bfloat16(x1 - f1);
    hi = ((unsigned)__bfloat16_as_ushort(h1) << 16) | (unsigned)__bfloat16_as_ushort(h0);
    lo = ((unsigned)__bfloat16_as_ushort(l1) << 16) | (unsigned)__bfloat16_as_ushort(l0);
}

__device__ __forceinline__ void split_store(float v, __nv_bfloat16* hi, __nv_bfloat16* lo, size_t idx)
{
    __nv_bfloat16 h = __float2bfloat16(v);
    hi[idx] = h;
    lo[idx] = __float2bfloat16(v - __bfloat162float(h));
}

__device__ __forceinline__ void mma_bf16(float c[4],
                                         unsigned a0, unsigned a1, unsigned a2, unsigned a3,
                                         unsigned b0, unsigned b1)
{
    asm volatile("mma.sync.aligned.m16n8k16.row.col.f32.bf16.bf16.f32 "
                 "{%0,%1,%2,%3}, {%4,%5,%6,%7}, {%8,%9}, {%0,%1,%2,%3};"
                 : "+f"(c[0]), "+f"(c[1]), "+f"(c[2]), "+f"(c[3])
                 : "r"(a0), "r"(a1), "r"(a2), "r"(a3), "r"(b0), "r"(b1));
}

__device__ __forceinline__ void ldsm4(unsigned &r0, unsigned &r1, unsigned &r2, unsigned &r3, unsigned addr)
{
    asm volatile("ldmatrix.sync.aligned.m8n8.x4.shared.b16 {%0,%1,%2,%3}, [%4];"
                 : "=r"(r0), "=r"(r1), "=r"(r2), "=r"(r3) : "r"(addr));
}

__device__ __forceinline__ void cpa16(unsigned saddr, const void* g)
{
    asm volatile("cp.async.ca.shared.global [%0], [%1], 16;" :: "r"(saddr), "l"(g));
}

// ---------------- merged weight split (all 5 weights, 1 launch) ----------
#define W1M4 (DD*DD/4)
#define W2M4 (DD*2*DD/4)
__global__ void conv_split_all(const float4* __restrict__ wq, const float4* __restrict__ wk,
                               const float4* __restrict__ wv, const float4* __restrict__ wo,
                               const float4* __restrict__ wp)
{
    int i = blockIdx.x * blockDim.x + threadIdx.x;
    const float4* src;
    __nv_bfloat16 *hi, *lo;
    int off;
    if (i < W1M4)            { src = wq; hi = gb_wq_h; lo = gb_wq_l; off = i; }
    else if (i < 2*W1M4)     { src = wk; hi = gb_wk_h; lo = gb_wk_l; off = i - W1M4; }
    else if (i < 3*W1M4)     { src = wv; hi = gb_wv_h; lo = gb_wv_l; off = i - 2*W1M4; }
    else if (i < 4*W1M4)     { src = wo; hi = gb_wo_h; lo = gb_wo_l; off = i - 3*W1M4; }
    else if (i < 4*W1M4+W2M4){ src = wp; hi = gb_wp_h; lo = gb_wp_l; off = i - 4*W1M4; }
    else return;
    float4 v = src[off];
    unsigned h0, l0, h1, l1;
    split_pack(v.x, v.y, h0, l0);
    split_pack(v.z, v.w, h1, l1);
    *(uint2*)(hi + (size_t)off*4) = make_uint2(h0, h1);
    *(uint2*)(lo + (size_t)off*4) = make_uint2(l0, l1);
}

// ---------------- LayerNorm: fp32 local + bf16 hi/lo globe ----------------
__global__ void ln_kernel(const float* __restrict__ x,
                          const float* __restrict__ ga, const float* __restrict__ ba,
                          const float* __restrict__ gb, const float* __restrict__ bb)
{
    __shared__ float red[256];
    int row = blockIdx.x;
    int t = threadIdx.x;
    const float* xr = x + (size_t)row * DD;
    float v[4];
    float s = 0.f;
#pragma unroll
    for (int k = 0; k < 4; k++) { v[k] = xr[t + 256*k]; s += v[k]; }
    red[t] = s; __syncthreads();
    for (int o = 128; o > 0; o >>= 1) { if (t < o) red[t] += red[t+o]; __syncthreads(); }
    float mean = red[0] * (1.0f/DD);
    __syncthreads();
    float s2 = 0.f;
#pragma unroll
    for (int k = 0; k < 4; k++) { float d0 = v[k]-mean; s2 += d0*d0; }
    red[t] = s2; __syncthreads();
    for (int o = 128; o > 0; o >>= 1) { if (t < o) red[t] += red[t+o]; __syncthreads(); }
    float rs = rsqrtf(red[0]*(1.0f/DD) + 1e-5f);
#pragma unroll
    for (int k = 0; k < 4; k++) {
        int c = t + 256*k;
        float nh = (v[k]-mean)*rs;
        size_t idx = (size_t)row*DD + c;
        g_local[idx] = nh*ga[c] + ba[c];
        split_store(nh*gb[c] + bb[c], gb_globe_h, gb_globe_l, idx);
    }
}

// ---------------- bf16x3 GEMM: cp.async + ldmatrix, double-buffered -------
// (R12-measured best configuration: 80B rows, 2-stage, .ca, dual-A fusion)
#define GSM_ROWB 80
#define GSM_PLANE 10240
#define GSM_BUF 40960
#define GEMM_SMEM_BYTES (2*GSM_BUF)

__global__ void __launch_bounds__(256, 2) gemm_bf16lm(
    const __nv_bfloat16* __restrict__ Ah, const __nv_bfloat16* __restrict__ Al,
    const __nv_bfloat16* __restrict__ A2h, const __nv_bfloat16* __restrict__ A2l,
    const __nv_bfloat16* __restrict__ Wh, const __nv_bfloat16* __restrict__ Wl,
    const float* __restrict__ bias, float* __restrict__ C,
    __nv_bfloat16* __restrict__ Chi, __nv_bfloat16* __restrict__ Clo,
    int N, int lda, int K, int ldw, int koff, int k1ch, int transv)
{
    extern __shared__ char sm8[];
    unsigned sbase = (unsigned)__cvta_generic_to_shared(sm8);

    int t = threadIdx.x;
    int wid = t >> 5, lane = t & 31;
    int warp_m = wid >> 2, warp_n = wid & 3;
    int bm = blockIdx.y * 128, bn = blockIdx.x * 128;
    int qq = lane >> 2, rr = lane & 3;

    int crow = t >> 1;
    int csp = t & 1;
    const __nv_bfloat16* gAh = Ah + (size_t)(bm + crow) * lda + csp*16;
    const __nv_bfloat16* gAl = Al + (size_t)(bm + crow) * lda + csp*16;
    const __nv_bfloat16* gA2h = A2h ? A2h + (size_t)(bm + crow) * lda + csp*16 : gAh;
    const __nv_bfloat16* gA2l = A2l ? A2l + (size_t)(bm + crow) * lda + csp*16 : gAl;
    const __nv_bfloat16* gWh = Wh + (size_t)(bn + crow) * ldw + koff + csp*16;
    const __nv_bfloat16* gWl = Wl + (size_t)(bn + crow) * ldw + koff + csp*16;
    unsigned dOff = crow*GSM_ROWB + csp*32;

    int mq = lane >> 3, j = lane & 7;
    unsigned aoff = (warp_m*64 + (mq&1)*8 + j)*GSM_ROWB + (mq>>1)*16;
    unsigned boff = (warp_n*32 + (mq>>1)*8 + j)*GSM_ROWB + (mq&1)*16;

    float acc[4][4][4];
#pragma unroll
    for (int im = 0; im < 4; im++)
#pragma unroll
        for (int in = 0; in < 4; in++)
#pragma unroll
            for (int r = 0; r < 4; r++) acc[im][in][r] = 0.f;

#define ISSUE(buf, kc) do { \
    unsigned d = sbase + (buf)*GSM_BUF + dOff; \
    const __nv_bfloat16* sh_ = ((kc) < k1ch) ? gAh + (size_t)(kc)*32 : gA2h + (size_t)((kc) - k1ch)*32; \
    const __nv_bfloat16* sl_ = ((kc) < k1ch) ? gAl + (size_t)(kc)*32 : gA2l + (size_t)((kc) - k1ch)*32; \
    cpa16(d,                   sh_); \
    cpa16(d+16,                sh_ + 8); \
    cpa16(d+GSM_PLANE,         sl_); \
    cpa16(d+GSM_PLANE+16,      sl_ + 8); \
    cpa16(d+2*GSM_PLANE,       gWh + (size_t)(kc)*32); \
    cpa16(d+2*GSM_PLANE+16,    gWh + (size_t)(kc)*32 + 8); \
    cpa16(d+3*GSM_PLANE,       gWl + (size_t)(kc)*32); \
    cpa16(d+3*GSM_PLANE+16,    gWl + (size_t)(kc)*32 + 8); \
    asm volatile("cp.async.commit_group;"); \
} while (0)

    int nch = K / 32;
    ISSUE(0, 0);
    if (nch > 1) ISSUE(1, 1);

    for (int c = 0; c < nch; c++) {
        int cur = c & 1;
        if (c + 1 < nch) asm volatile("cp.async.wait_group 1;");
        else             asm volatile("cp.async.wait_group 0;");
        __syncthreads();

        unsigned pah = sbase + cur*GSM_BUF + aoff;
        unsigned pal = pah + GSM_PLANE;
        unsigned pbh = sbase + cur*GSM_BUF + 2*GSM_PLANE + boff;
        unsigned pbl = pbh + GSM_PLANE;
#pragma unroll
        for (int ks = 0; ks < 2; ks++) {
            unsigned kb = ks*32;
            unsigned bh0[4], bh1[4], bl0[4], bl1[4];
            {
                unsigned r0,r1,r2,r3;
                ldsm4(r0,r1,r2,r3, pbh + kb);
                bh0[0]=r0; bh1[0]=r1; bh0[1]=r2; bh1[1]=r3;
                ldsm4(r0,r1,r2,r3, pbh + 1280 + kb);
                bh0[2]=r0; bh1[2]=r1; bh0[3]=r2; bh1[3]=r3;
                ldsm4(r0,r1,r2,r3, pbl + kb);
                bl0[0]=r0; bl1[0]=r1; bl0[1]=r2; bl1[1]=r3;
                ldsm4(r0,r1,r2,r3, pbl + 1280 + kb);
                bl0[2]=r0; bl1[2]=r1; bl0[3]=r2; bl1[3]=r3;
            }
#pragma unroll
            for (int im = 0; im < 4; im++) {
                unsigned ah0,ah1,ah2,ah3, al0,al1,al2,al3;
                ldsm4(ah0,ah1,ah2,ah3, pah + im*1280 + kb);
                ldsm4(al0,al1,al2,al3, pal + im*1280 + kb);
#pragma unroll
                for (int in = 0; in < 4; in++) {
                    mma_bf16(acc[im][in], ah0,ah1,ah2,ah3, bh0[in], bh1[in]);
                    mma_bf16(acc[im][in], ah0,ah1,ah2,ah3, bl0[in], bl1[in]);
                    mma_bf16(acc[im][in], al0,al1,al2,al3, bh0[in], bh1[in]);
                }
            }
        }
        __syncthreads();
        if (c + 2 < nch) ISSUE(cur, c + 2);
    }
#undef ISSUE

    // epilogue
#pragma unroll
    for (int im = 0; im < 4; im++) {
        int r0 = bm + warp_m*64 + im*16 + qq;
#pragma unroll
        for (int in = 0; in < 4; in++) {
            int c0 = bn + warp_n*32 + in*8 + 2*rr;
            float b0v = bias ? bias[c0]   : 0.f;
            float b1v = bias ? bias[c0+1] : 0.f;
#pragma unroll
            for (int half = 0; half < 2; half++) {
                int m = r0 + half*8;
                float v0 = acc[im][in][2*half + 0] + b0v;
                float v1 = acc[im][in][2*half + 1] + b1v;
                if (transv) {
                    size_t i0 = ((size_t)((m>>10)*HH + (c0>>6))*HD + (c0&63))*SS + (m&1023);
                    size_t i1 = ((size_t)((m>>10)*HH + ((c0+1)>>6))*HD + ((c0+1)&63))*SS + (m&1023);
                    split_store(v0, Chi, Clo, i0);
                    split_store(v1, Chi, Clo, i1);
                } else {
                    size_t idx = (size_t)m * N + c0;
                    if (C) { C[idx] = v0; C[idx+1] = v1; }
                    if (Chi) {
                        split_store(v0, Chi, Clo, idx);
                        split_store(v1, Chi, Clo, idx+1);
                    }
                }
            }
        }
    }
}

// ---------------- Global causal attention: 2 barriers/iter, V planes ------
#define AW 36
#define A_QH 0
#define A_QL 2304
#define A_KH 4608
#define A_KL 6912
#define A_VH 9216
#define A_VL 11520
#define A_PH 13824
#define A_PL 16128
#define A_ST 18432               // float [64][66] = 4224
#define A_MS (18432 + 4224)
#define ATT_SMEM_WORDS (18432 + 4224 + 192)
#define ATT_SMEM_BYTES (ATT_SMEM_WORDS*4)

__global__ void __launch_bounds__(256, 2) attn_global_mma()
{
    extern __shared__ unsigned usm[];
    float* STm = (float*)(usm + A_ST);
    float* m_s = (float*)(usm + A_MS);
    float* l_s = m_s + 64;
    float* al_s = l_s + 64;

    int qt = 15 - (int)blockIdx.x;
    int bh = blockIdx.y;
    int b = bh >> 4, h = bh & 15;
    int t = threadIdx.x;
    int lane = t & 31, wid = t >> 5;
    int tx = t & 15, ty = t >> 4;
    int warp_m = wid & 3, warp_n = wid >> 2;
    int qq = lane >> 2, rr = lane & 3;
    int q0 = qt * 64;
    size_t baseQ = (size_t)b * SS * DD + h * HD;
    size_t baseVT = ((size_t)(b*HH + h)) * HD * SS;

    // load Q tile hi/lo
#pragma unroll
    for (int i = 0; i < 4; i++) {
        int r = ty + 16*i;
        size_t gi = baseQ + (size_t)(q0 + r) * DD + 4*tx;
        uint2 vh = *(const uint2*)(gb_q_h + gi);
        uint2 vl = *(const uint2*)(gb_q_l + gi);
        usm[A_QH + r*AW + 2*tx] = vh.x;  usm[A_QH + r*AW + 2*tx + 1] = vh.y;
        usm[A_QL + r*AW + 2*tx] = vl.x;  usm[A_QL + r*AW + 2*tx + 1] = vl.y;
    }
    if (t < 64) { m_s[t] = -3.0e38f; l_s[t] = 0.f; }

    float oacc[4][4];
#pragma unroll
    for (int nn = 0; nn < 4; nn++)
#pragma unroll
        for (int r = 0; r < 4; r++) oacc[nn][r] = 0.f;

    // prefetch + store K(0) to smem
    uint2 kvh[4], kvl[4];
#pragma unroll
    for (int i = 0; i < 4; i++) {
        int r = ty + 16*i;
        size_t gi = baseQ + (size_t)r * DD + 4*tx;
        kvh[i] = *(const uint2*)(gb_k_h + gi);
        kvl[i] = *(const uint2*)(gb_k_l + gi);
    }
#pragma unroll
    for (int i = 0; i < 4; i++) {
        int r = ty + 16*i;
        usm[A_KH + r*AW + 2*tx] = kvh[i].x;  usm[A_KH + r*AW + 2*tx + 1] = kvh[i].y;
        usm[A_KL + r*AW + 2*tx] = kvl[i].x;  usm[A_KL + r*AW + 2*tx + 1] = kvl[i].y;
    }
    __syncthreads();

    for (int kt = 0; kt <= qt; kt++) {
        int k0 = kt * 64;
        // ---- phase 1: S^T = K @ Q^T -> STm; issue V(kt) + K(kt+1) loads ----
        {
            float c4[4][4];
#pragma unroll
            for (int nn = 0; nn < 4; nn++)
#pragma unroll
                for (int r = 0; r < 4; r++) c4[nn][r] = 0.f;
#pragma unroll
            for (int ks = 0; ks < 4; ks++) {
                int kw = ks*8;
                int ar = warp_m*16 + qq;
                unsigned ah0 = usm[A_KH +  ar   *AW + kw+rr];
                unsigned ah1 = usm[A_KH + (ar+8)*AW + kw+rr];
                unsigned ah2 = usm[A_KH +  ar   *AW + kw+4+rr];
                unsigned ah3 = usm[A_KH + (ar+8)*AW + kw+4+rr];
                unsigned al0 = usm[A_KL +  ar   *AW + kw+rr];
                unsigned al1 = usm[A_KL + (ar+8)*AW + kw+rr];
                unsigned al2 = usm[A_KL +  ar   *AW + kw+4+rr];
                unsigned al3 = usm[A_KL + (ar+8)*AW + kw+4+rr];
#pragma unroll
                for (int nn = 0; nn < 4; nn++) {
                    int br = warp_n*32 + nn*8 + qq;
                    unsigned bh0 = usm[A_QH + br*AW + kw+rr];
                    unsigned bh1 = usm[A_QH + br*AW + kw+4+rr];
                    unsigned bl0 = usm[A_QL + br*AW + kw+rr];
                    unsigned bl1 = usm[A_QL + br*AW + kw+4+rr];
                    mma_bf16(c4[nn], ah0, ah1, ah2, ah3, bh0, bh1);
                    mma_bf16(c4[nn], ah0, ah1, ah2, ah3, bl0, bl1);
                    mma_bf16(c4[nn], al0, al1, al2, al3, bh0, bh1);
                }
            }
            int krow = warp_m*16 + qq;
#pragma unroll
            for (int nn = 0; nn < 4; nn++) {
                int qc = warp_n*32 + nn*8 + 2*rr;
                STm[ krow   *66 + qc    ] = c4[nn][0];
                STm[ krow   *66 + qc + 1] = c4[nn][1];
                STm[(krow+8)*66 + qc    ] = c4[nn][2];
                STm[(krow+8)*66 + qc + 1] = c4[nn][3];
            }
        }
        uint2 vvh[4], vvl[4];
#pragma unroll
        for (int i = 0; i < 4; i++) {
            int d = ty + 16*i;
            size_t gi = baseVT + (size_t)d * SS + k0 + 4*tx;
            vvh[i] = *(const uint2*)(gb_v_h + gi);
            vvl[i] = *(const uint2*)(gb_v_l + gi);
        }
        if (kt < qt) {
#pragma unroll
            for (int i = 0; i < 4; i++) {
                int r = ty + 16*i;
                size_t gi = baseQ + (size_t)(k0 + 64 + r) * DD + 4*tx;
                kvh[i] = *(const uint2*)(gb_k_h + gi);
                kvl[i] = *(const uint2*)(gb_k_l + gi);
            }
        }
        __syncthreads();   // sync a

        // ---- phase 2: softmax (STm->P); store V -> VH/VL; store K(kt+1) ----
        {
            int row = t >> 2, sub = t & 3;
            int qglob = q0 + row;
            float mo = m_s[row];
            float mx = mo;
            float ev[16];
#pragma unroll
            for (int j2 = 0; j2 < 16; j2++) {
                int key = sub*16 + j2;
                float sv = STm[key*66 + row] * 0.125f;
                if (k0 + key > qglob) sv = -1.0e30f;
                ev[j2] = sv;
                mx = fmaxf(mx, sv);
            }
            mx = fmaxf(mx, __shfl_xor_sync(0xffffffffu, mx, 1));
            mx = fmaxf(mx, __shfl_xor_sync(0xffffffffu, mx, 2));
            float sum = 0.f;
#pragma unroll
            for (int j2 = 0; j2 < 16; j2++) {
                float e = __expf(ev[j2] - mx);
                ev[j2] = e; sum += e;
            }
#pragma unroll
            for (int j2 = 0; j2 < 8; j2++) {
                unsigned hi, lo;
                split_pack(ev[2*j2], ev[2*j2+1], hi, lo);
                usm[A_PH + row*AW + sub*8 + j2] = hi;
                usm[A_PL + row*AW + sub*8 + j2] = lo;
            }
            sum += __shfl_xor_sync(0xffffffffu, sum, 1);
            sum += __shfl_xor_sync(0xffffffffu, sum, 2);
            if (sub == 0) {
                float alpha = __expf(mo - mx);
                m_s[row] = mx;
                l_s[row] = l_s[row] * alpha + sum;
                al_s[row] = alpha;
            }
        }
#pragma unroll
        for (int i = 0; i < 4; i++) {
            int d = ty + 16*i;
            usm[A_VH + d*AW + 2*tx] = vvh[i].x;  usm[A_VH + d*AW + 2*tx + 1] = vvh[i].y;
            usm[A_VL + d*AW + 2*tx] = vvl[i].x;  usm[A_VL + d*AW + 2*tx + 1] = vvl[i].y;
        }
        if (kt < qt) {
#pragma unroll
            for (int i = 0; i < 4; i++) {
                int r = ty + 16*i;
                usm[A_KH + r*AW + 2*tx] = kvh[i].x;  usm[A_KH + r*AW + 2*tx + 1] = kvh[i].y;
                usm[A_KL + r*AW + 2*tx] = kvl[i].x;  usm[A_KL + r*AW + 2*tx + 1] = kvl[i].y;
            }
        }
        __syncthreads();   // sync b

        // ---- phase 3: O *= alpha ; O += P @ V ----
        {
            int qr = warp_m*16 + qq;
            float a0 = al_s[qr], a1 = al_s[qr + 8];
#pragma unroll
            for (int nn = 0; nn < 4; nn++) {
                oacc[nn][0] *= a0; oacc[nn][1] *= a0;
                oacc[nn][2] *= a1; oacc[nn][3] *= a1;
            }
#pragma unroll
            for (int ks = 0; ks < 4; ks++) {
                int kw = ks*8;
                int ar = warp_m*16 + qq;
                unsigned ah0 = usm[A_PH +  ar   *AW + kw+rr];
                unsigned ah1 = usm[A_PH + (ar+8)*AW + kw+rr];
                unsigned ah2 = usm[A_PH +  ar   *AW + kw+4+rr];
                unsigned ah3 = usm[A_PH + (ar+8)*AW + kw+4+rr];
                unsigned al0 = usm[A_PL +  ar   *AW + kw+rr];
                unsigned al1 = usm[A_PL + (ar+8)*AW + kw+rr];
                unsigned al2 = usm[A_PL +  ar   *AW + kw+4+rr];
                unsigned al3 = usm[A_PL + (ar+8)*AW + kw+4+rr];
#pragma unroll
                for (int nn = 0; nn < 4; nn++) {
                    int br = warp_n*32 + nn*8 + qq;
                    unsigned bh0 = usm[A_VH + br*AW + kw+rr];
                    unsigned bh1 = usm[A_VH + br*AW + kw+4+rr];
                    unsigned bl0 = usm[A_VL + br*AW + kw+rr];
                    unsigned bl1 = usm[A_VL + br*AW + kw+4+rr];
                    mma_bf16(oacc[nn], ah0, ah1, ah2, ah3, bh0, bh1);
                    mma_bf16(oacc[nn], ah0, ah1, ah2, ah3, bl0, bl1);
                    mma_bf16(oacc[nn], al0, al1, al2, al3, bh0, bh1);
                }
            }
        }
    }

    // write O hi/lo (normalized)
    {
        int qr = warp_m*16 + qq;
        float inv0 = 1.f / l_s[qr];
        float inv1 = 1.f / l_s[qr + 8];
#pragma unroll
        for (int nn = 0; nn < 4; nn++) {
            int dc = warp_n*32 + nn*8 + 2*rr;
            size_t i0 = baseQ + (size_t)(q0 + qr) * DD + dc;
            size_t i1 = baseQ + (size_t)(q0 + qr + 8) * DD + dc;
            split_store(oacc[nn][0] * inv0, gb_attn_h, gb_attn_l, i0);
            split_store(oacc[nn][1] * inv0, gb_attn_h, gb_attn_l, i0+1);
            split_store(oacc[nn][2] * inv1, gb_attn_h, gb_attn_l, i1);
            split_store(oacc[nn][3] * inv1, gb_attn_h, gb_attn_l, i1+1);
        }
    }
}

// ---------------- Predictor (two-stage, parallel, deterministic) ----------
__global__ void pred_partA()
{
    int b = blockIdx.x, ch = blockIdx.y;
    int t = threadIdx.x;
#pragma unroll
    for (int c = 0; c < 4; c++) {
        int col = t + 256*c;
        float s = 0.f;
        const float* p = g_gout + ((size_t)b*SS + ch*64) * DD + col;
        for (int r = 0; r < 64; r++) s += p[(size_t)r * DD];
        g_pp[((size_t)b*16 + ch)*DD + col] = s;
    }
}

__global__ void pred_partB(const float* __restrict__ Wp, const float* __restrict__ bp)
{
    __shared__ float red[256];
    int b = blockIdx.x;
    int t = threadIdx.x;
    float part = 0.f;
#pragma unroll
    for (int c = 0; c < 4; c++) {
        int col = t + 256*c;
        float s = 0.f;
#pragma unroll
        for (int ch = 0; ch < 16; ch++)
            s += g_pp[((size_t)b*16 + ch)*DD + col];
        part += (s * (1.0f/SS)) * Wp[col];
    }
    red[t] = part; __syncthreads();
    for (int o = 128; o > 0; o >>= 1) { if (t < o) red[t] += red[t+o]; __syncthreads(); }
    if (t == 0) {
        float z = red[0] + bp[0];
        g_base[b] = 1.f / (1.f + expf(-z));
    }
}

// ---------------- Span params ----------------
__global__ void params_kernel()
{
    float smf = (g_base[0] + g_base[1] + g_base[2] + g_base[3]) * 0.25f;
    double sm = (double)smf;
    int win = (int)(256.0 * sm);      if (win < 1) win = 1;
    int span_len = (int)(512.0 * sm); if (span_len < 1) span_len = 1;
    int lm = 512;
    if (span_len < lm) lm = span_len;
    if (win < lm) lm = win;
    g_params.win = win;
    g_params.span_len = span_len;
    g_params.local_max = lm;
    g_params.span_mean = smf;
    g_params.temp = (float)(1.0 + 0.01 * (1.0 - sm));
}

// ---------------- Local span attention: register-resident online softmax --
// Thread (ty,tx) owns Q rows {2ty, 2ty+1} for the whole kt loop; the 16
// threads of a row-pair are a contiguous half-warp -> shfl_xor 1/2/4/8
// row reductions. m/l/alpha live in registers. 3 barriers per kt iteration.
__global__ void __launch_bounds__(256) attn_local_kernel()
{
    __shared__ float Qs[32][65];
    __shared__ float Ks[64][65];
    __shared__ float Ss[32][65];

    SpanParams p = g_params;
    int bh = blockIdx.x;  int b = bh >> 4, h = bh & 15;
    int qt = blockIdx.y;
    int t = threadIdx.x;
    int tx = t & 15, ty = t >> 4;
    size_t base = (size_t)b * SS * DD + h * HD;
    float sc = 0.35355339059327373f / p.temp;

    for (int w = blockIdx.z; w * p.win < SS; w += (int)gridDim.z) {
        int st = w * p.win;
        int en = st + p.win; if (en > SS) en = SS;
        int wlen = en - st;
        int ks0 = st - p.span_len + p.win; if (ks0 < 0) ks0 = 0;
        int ke = st + p.span_len; if (ke > SS) ke = SS;
        int klen = ke - ks0;
        int eff = (int)((double)wlen * (double)p.span_mean);
        if (eff > wlen) eff = wlen;
        if (eff > klen) eff = klen;
        if (eff > p.local_max) eff = p.local_max;
        int q0 = qt * 32;
        if (q0 >= wlen) continue;
        bool docompute = (eff > 0 && q0 < eff);
        int qcnt = 0;
        if (docompute) { qcnt = eff - q0; if (qcnt > 32) qcnt = 32; }

        float accO[2][4];
#pragma unroll
        for (int i = 0; i < 2; i++)
#pragma unroll
            for (int j = 0; j < 4; j++) accO[i][j] = 0.f;
        float m0 = -3.0e38f, m1 = -3.0e38f, l0 = 0.f, l1 = 0.f;

        if (docompute) {
            {
                int col = tx * 4;
#pragma unroll
                for (int rr2 = 0; rr2 < 2; rr2++) {
                    int r = ty + rr2*16;
                    float4 qv = make_float4(0.f,0.f,0.f,0.f);
                    if (r < qcnt)
                        qv = *(const float4*)(g_local + base + (size_t)(st + q0 + r) * DD + col);
                    Qs[r][col+0]=qv.x; Qs[r][col+1]=qv.y; Qs[r][col+2]=qv.z; Qs[r][col+3]=qv.w;
                }
            }

            int nkt = (eff + 63) >> 6;
            for (int kt = 0; kt < nkt; kt++) {
                {
                    int col = tx * 4;
#pragma unroll
                    for (int rr2 = 0; rr2 < 4; rr2++) {
                        int r = ty + rr2*16;
                        float4 kv = make_float4(0.f,0.f,0.f,0.f);
                        if (kt*64 + r < eff)
                            kv = *(const float4*)(g_local + base + (size_t)(ks0 + kt*64 + r) * DD + col);
                        Ks[r][col+0]=kv.x; Ks[r][col+1]=kv.y; Ks[r][col+2]=kv.z; Ks[r][col+3]=kv.w;
                    }
                }
                __syncthreads();   // Ks + (first iter) Qs ready

                // scores for own 2 rows x 4 cols
                float sacc[2][4];
#pragma unroll
                for (int i = 0; i < 2; i++)
#pragma unroll
                    for (int j = 0; j < 4; j++) sacc[i][j] = 0.f;
#pragma unroll 8
                for (int kk = 0; kk < 64; kk++) {
                    float qv0 = Qs[2*ty+0][kk];
                    float qv1 = Qs[2*ty+1][kk];
#pragma unroll
                    for (int j = 0; j < 4; j++) {
                        float kv = Ks[4*tx+j][kk];
                        sacc[0][j] += qv0*kv;
                        sacc[1][j] += qv1*kv;
                    }
                }
                // scale + mask in registers
#pragma unroll
                for (int i = 0; i < 2; i++)
#pragma unroll
                    for (int j = 0; j < 4; j++) {
                        float sv = sacc[i][j] * sc;
                        if (kt*64 + 4*tx + j >= eff) sv = -1.0e30f;
                        sacc[i][j] = sv;
                    }
                // register-resident online softmax over the 16-lane half-warp
                float mx0 = m0, mx1 = m1;
#pragma unroll
                for (int j = 0; j < 4; j++) {
                    mx0 = fmaxf(mx0, sacc[0][j]);
                    mx1 = fmaxf(mx1, sacc[1][j]);
                }
#pragma unroll
                for (int d = 1; d < 16; d <<= 1) {
                    mx0 = fmaxf(mx0, __shfl_xor_sync(0xffffffffu, mx0, d));
                    mx1 = fmaxf(mx1, __shfl_xor_sync(0xffffffffu, mx1, d));
                }
                float a0 = __expf(m0 - mx0);
                float a1 = __expf(m1 - mx1);
                float s0 = 0.f, s1 = 0.f;
#pragma unroll
                for (int j = 0; j < 4; j++) {
                    float e0 = __expf(sacc[0][j] - mx0);
                    float e1 = __expf(sacc[1][j] - mx1);
                    Ss[2*ty+0][4*tx+j] = e0;
                    Ss[2*ty+1][4*tx+j] = e1;
                    s0 += e0; s1 += e1;
                }
#pragma unroll
                for (int d = 1; d < 16; d <<= 1) {
                    s0 += __shfl_xor_sync(0xffffffffu, s0, d);
                    s1 += __shfl_xor_sync(0xffffffffu, s1, d);
                }
                m0 = mx0; m1 = mx1;
                l0 = l0*a0 + s0;
                l1 = l1*a1 + s1;
                __syncthreads();   // exp values in Ss visible to all

                // O update
#pragma unroll
                for (int j = 0; j < 4; j++) { accO[0][j] *= a0; accO[1][j] *= a1; }
#pragma unroll 4
                for (int c = 0; c < 64; c++) {
                    float p0 = Ss[2*ty+0][c];
                    float p1 = Ss[2*ty+1][c];
#pragma unroll
                    for (int j = 0; j < 4; j++) {
                        float vv = Ks[c][4*tx+j];
                        accO[0][j] += p0*vv;
                        accO[1][j] += p1*vv;
                    }
                }
                __syncthreads();   // Ks/Ss free for next iteration
            }
        }

        // store: attention rows [0, qcnt), zeros for rows [qcnt, wlen-q0)
#pragma unroll
        for (int i = 0; i < 2; i++) {
            int rloc = 2*ty + i;
            if (q0 + rloc >= wlen) continue;
            size_t idx = base + (size_t)(st + q0 + rloc) * DD + 4*tx;
            if (rloc < qcnt) {
                float inv = 1.f / (i == 0 ? l0 : l1);
#pragma unroll
                for (int j = 0; j < 4; j++)
                    split_store(accO[i][j] * inv, gb_lout_h, gb_lout_l, idx + j);
            } else {
                *(uint2*)(gb_lout_h + idx) = make_uint2(0u, 0u);
                *(uint2*)(gb_lout_l + idx) = make_uint2(0u, 0u);
            }
        }
    }
}

// ---------------- launch ----------------
extern "C" void kernel_launch(void* const* d_in, const int* in_sizes, int n_in,
                              void* d_out, int out_size)
{
    const float* x     = (const float*)d_in[0];
    const float* ln_ag = (const float*)d_in[1];
    const float* ln_ab = (const float*)d_in[2];
    const float* ln_bg = (const float*)d_in[3];
    const float* ln_bb = (const float*)d_in[4];
    const float* Wq    = (const float*)d_in[5];
    const float* bq    = (const float*)d_in[6];
    const float* Wk    = (const float*)d_in[7];
    const float* Wv    = (const float*)d_in[8];
    const float* bv    = (const float*)d_in[9];
    const float* Wo    = (const float*)d_in[10];
    const float* bo    = (const float*)d_in[11];
    const float* Wp    = (const float*)d_in[12];
    const float* bp    = (const float*)d_in[13];
    const float* Wproj = (const float*)d_in[14];
    const float* bproj = (const float*)d_in[15];
    float* out = (float*)d_out;

    void *p_gout, *p_lh, *p_ll;
    void *p_gh, *p_gl, *p_qh, *p_ql, *p_kh, *p_kl, *p_vh, *p_vl;
    void *p_ah, *p_al, *p_oh, *p_ol;
    void *p_wqh, *p_wql, *p_wkh, *p_wkl, *p_wvh, *p_wvl, *p_woh, *p_wol, *p_wph, *p_wpl;
    cudaGetSymbolAddress(&p_gout, g_gout);
    cudaGetSymbolAddress(&p_lh, gb_lout_h);  cudaGetSymbolAddress(&p_ll, gb_lout_l);
    cudaGetSymbolAddress(&p_gh, gb_globe_h); cudaGetSymbolAddress(&p_gl, gb_globe_l);
    cudaGetSymbolAddress(&p_qh, gb_q_h);     cudaGetSymbolAddress(&p_ql, gb_q_l);
    cudaGetSymbolAddress(&p_kh, gb_k_h);     cudaGetSymbolAddress(&p_kl, gb_k_l);
    cudaGetSymbolAddress(&p_vh, gb_v_h);     cudaGetSymbolAddress(&p_vl, gb_v_l);
    cudaGetSymbolAddress(&p_ah, gb_attn_h);  cudaGetSymbolAddress(&p_al, gb_attn_l);
    cudaGetSymbolAddress(&p_oh, gb_gout_h);  cudaGetSymbolAddress(&p_ol, gb_gout_l);
    cudaGetSymbolAddress(&p_wqh, gb_wq_h);   cudaGetSymbolAddress(&p_wql, gb_wq_l);
    cudaGetSymbolAddress(&p_wkh, gb_wk_h);   cudaGetSymbolAddress(&p_wkl, gb_wk_l);
    cudaGetSymbolAddress(&p_wvh, gb_wv_h);   cudaGetSymbolAddress(&p_wvl, gb_wv_l);
    cudaGetSymbolAddress(&p_woh, gb_wo_h);   cudaGetSymbolAddress(&p_wol, gb_wo_l);
    cudaGetSymbolAddress(&p_wph, gb_wp_h);   cudaGetSymbolAddress(&p_wpl, gb_wp_l);

    cudaFuncSetAttribute(gemm_bf16lm, cudaFuncAttributeMaxDynamicSharedMemorySize, GEMM_SMEM_BYTES);
    cudaFuncSetAttribute(attn_global_mma, cudaFuncAttributeMaxDynamicSharedMemorySize, ATT_SMEM_BYTES);

    // 0) LayerNorms
    ln_kernel<<<MROWS, 256>>>(x, ln_ag, ln_ab, ln_bg, ln_bb);

    // 1) merged weight split (all 5 weights)
    const int NCONV = 4*W1M4 + W2M4;
    conv_split_all<<<(NCONV+255)/256, 256>>>((const float4*)Wq, (const float4*)Wk,
                                             (const float4*)Wv, (const float4*)Wo,
                                             (const float4*)Wproj);

    // 2-4) QKV projections (bf16 hi/lo outputs; V transposed)
    dim3 ggrid(DD/128, MROWS/128);
    gemm_bf16lm<<<ggrid, 256, GEMM_SMEM_BYTES>>>((__nv_bfloat16*)p_gh, (__nv_bfloat16*)p_gl,
        nullptr, nullptr,
        (__nv_bfloat16*)p_wqh, (__nv_bfloat16*)p_wql, bq, nullptr,
        (__nv_bfloat16*)p_qh, (__nv_bfloat16*)p_ql, DD, DD, DD, DD, 0, 32, 0);
    gemm_bf16lm<<<ggrid, 256, GEMM_SMEM_BYTES>>>((__nv_bfloat16*)p_gh, (__nv_bfloat16*)p_gl,
        nullptr, nullptr,
        (__nv_bfloat16*)p_wkh, (__nv_bfloat16*)p_wkl, nullptr, nullptr,
        (__nv_bfloat16*)p_kh, (__nv_bfloat16*)p_kl, DD, DD, DD, DD, 0, 32, 0);
    gemm_bf16lm<<<ggrid, 256, GEMM_SMEM_BYTES>>>((__nv_bfloat16*)p_gh, (__nv_bfloat16*)p_gl,
        nullptr, nullptr,
        (__nv_bfloat16*)p_wvh, (__nv_bfloat16*)p_wvl, bv, nullptr,
        (__nv_bfloat16*)p_vh, (__nv_bfloat16*)p_vl, DD, DD, DD, DD, 0, 32, 1);

    // 5) Global causal attention (2 barriers/iter, K prefetch, V planes)
    attn_global_mma<<<dim3(16, BB*HH), 256, ATT_SMEM_BYTES>>>();

    // 6) Output projection (fp32 gout for predictor + hi/lo for Wproj)
    gemm_bf16lm<<<ggrid, 256, GEMM_SMEM_BYTES>>>((__nv_bfloat16*)p_ah, (__nv_bfloat16*)p_al,
        nullptr, nullptr,
        (__nv_bfloat16*)p_woh, (__nv_bfloat16*)p_wol, bo, (float*)p_gout,
        (__nv_bfloat16*)p_oh, (__nv_bfloat16*)p_ol, DD, DD, DD, DD, 0, 32, 0);

    // 7-9) Span predictor + params
    pred_partA<<<dim3(BB, 16), 256>>>();
    pred_partB<<<BB, 256>>>(Wp, bp);
    params_kernel<<<1, 1>>>();

    // 10) Local span attention (register-resident softmax; zero-fills tail)
    attn_local_kernel<<<dim3(BB*HH, 8, 16), 256>>>();

    // 11) Fused final projection: out = [local_out | globe_out] @ Wproj^T + bproj
    gemm_bf16lm<<<ggrid, 256, GEMM_SMEM_BYTES>>>((__nv_bfloat16*)p_lh, (__nv_bfloat16*)p_ll,
        (__nv_bfloat16*)p_oh, (__nv_bfloat16*)p_ol,
        (__nv_bfloat16*)p_wph, (__nv_bfloat16*)p_wpl, bproj, out,
        nullptr, nullptr, DD, DD, 2*DD, 2*DD, 0, 32, 0);
}